// round 1
// baseline (speedup 1.0000x reference)
#include <cuda_runtime.h>
#include <math.h>

// Model constants (fixed by the problem).
#define Dm   512
#define Hn   8
#define HDd  64
#define Sg   196
#define MAXT 4096
#define QG   14      // queries per attention block; 14 | 196 so no segment straddle
#define LMAX 1280    // max padded segment length (max seg = 6*196 = 1176 -> 19 tiles = 1216)

// Scratch: Q, K, V, O_attn  (4 * 4096 * 512 fp32 = 32 MB) + segment bounds.
__device__ float g_scratch[4 * MAXT * Dm];
__device__ int   g_seg[2 * MAXT];

// ---------------------------------------------------------------------------
// Segment setup: per-token [beg, end) from channels[] (device-resident).
// ---------------------------------------------------------------------------
__global__ void setup_kernel(const int* __restrict__ channels, int n_ch, int T,
                             int* __restrict__ segbeg, int* __restrict__ segend) {
    int t = blockIdx.x * blockDim.x + threadIdx.x;
    if (t >= T) return;
    int beg = 0, end = 0;
    for (int i = 0; i < n_ch; i++) {
        int len = channels[i] * Sg;
        end = beg + len;
        if (t < end) break;
        beg = end;
    }
    segbeg[t] = beg;
    segend[t] = end;
}

// ---------------------------------------------------------------------------
// fp32 SGEMM: C[m,n] = (A[m,:] (+ A2[m,:])) @ W[:,n] + bias[n]
// BM=BN=128, BK=16, 256 threads, 8x8 per-thread tile, float4 smem paths.
// ---------------------------------------------------------------------------
#define BM 128
#define BN 128
#define BK 16

__global__ __launch_bounds__(256, 2)
void gemm_kernel(const float* __restrict__ A, const float* __restrict__ A2,
                 const float* __restrict__ W, const float* __restrict__ bias,
                 float* __restrict__ C, int M) {
    __shared__ float As[BK][BM + 4];
    __shared__ float Bs[BK][BN + 4];
    const int m0 = blockIdx.x * BM, n0 = blockIdx.y * BN;
    const int tid = threadIdx.x;
    const int tx = tid & 15, ty = tid >> 4;

    float acc[8][8];
#pragma unroll
    for (int r = 0; r < 8; r++)
#pragma unroll
        for (int c = 0; c < 8; c++) acc[r][c] = 0.f;

    for (int k0 = 0; k0 < Dm; k0 += BK) {
        // A tile 128x16 -> As[k][m] (transposed), 2 float4 loads per thread
#pragma unroll
        for (int i = 0; i < 2; i++) {
            int idx = tid * 2 + i;
            int row = idx >> 2, quad = idx & 3;
            int m = m0 + row;
            float4 a = make_float4(0.f, 0.f, 0.f, 0.f);
            if (m < M) {
                a = *(const float4*)(A + (size_t)m * Dm + k0 + quad * 4);
                if (A2) {
                    float4 p = *(const float4*)(A2 + (size_t)m * Dm + k0 + quad * 4);
                    a.x += p.x; a.y += p.y; a.z += p.z; a.w += p.w;
                }
            }
            As[quad * 4 + 0][row] = a.x;
            As[quad * 4 + 1][row] = a.y;
            As[quad * 4 + 2][row] = a.z;
            As[quad * 4 + 3][row] = a.w;
        }
        // B tile 16x128 -> Bs[k][n], 2 float4 loads per thread
#pragma unroll
        for (int i = 0; i < 2; i++) {
            int idx = tid * 2 + i;
            int kr = idx >> 5, quad = idx & 31;
            float4 b = *(const float4*)(W + (size_t)(k0 + kr) * Dm + n0 + quad * 4);
            *(float4*)&Bs[kr][quad * 4] = b;
        }
        __syncthreads();

#pragma unroll
        for (int kk = 0; kk < BK; kk++) {
            float a[8], b[8];
            *(float4*)&a[0] = *(const float4*)&As[kk][ty * 8];
            *(float4*)&a[4] = *(const float4*)&As[kk][ty * 8 + 4];
            *(float4*)&b[0] = *(const float4*)&Bs[kk][tx * 8];
            *(float4*)&b[4] = *(const float4*)&Bs[kk][tx * 8 + 4];
#pragma unroll
            for (int r = 0; r < 8; r++)
#pragma unroll
                for (int c = 0; c < 8; c++)
                    acc[r][c] += a[r] * b[c];
        }
        __syncthreads();
    }

#pragma unroll
    for (int r = 0; r < 8; r++) {
        int m = m0 + ty * 8 + r;
        if (m >= M) continue;
#pragma unroll
        for (int c = 0; c < 8; c += 4) {
            int n = n0 + tx * 8 + c;
            float4 bv = *(const float4*)(bias + n);
            float4 o;
            o.x = acc[r][c + 0] + bv.x;
            o.y = acc[r][c + 1] + bv.y;
            o.z = acc[r][c + 2] + bv.z;
            o.w = acc[r][c + 3] + bv.w;
            *(float4*)(C + (size_t)m * Dm + n) = o;
        }
    }
}

// ---------------------------------------------------------------------------
// Fused attention: block = (14-query group, head). Exact two-pass softmax with
// the whole score strip resident in SMEM. Segments never straddle a block.
// ---------------------------------------------------------------------------
__global__ __launch_bounds__(256)
void attn_kernel(const float* __restrict__ Q, const float* __restrict__ K,
                 const float* __restrict__ V, float* __restrict__ O,
                 const int* __restrict__ segbeg, const int* __restrict__ segend) {
    extern __shared__ float sm[];
    float* Ps = sm;                      // [QG][LMAX] scores
    float* Qs = Ps + QG * LMAX;          // [QG][68]
    float* Ks = Qs + QG * 68;            // [64][68]  (reused for V)

    const int q0 = blockIdx.x * QG;
    const int h  = blockIdx.y;
    const int tid = threadIdx.x;
    const int beg = segbeg[q0];
    const int end = segend[q0];
    const int nt = (end - beg + 63) >> 6;
    const int Lp = nt << 6;

    // Load Q tile [QG x 64]
    for (int idx = tid; idx < QG * 16; idx += 256) {
        int r = idx >> 4, quad = idx & 15;
        float4 q4 = *(const float4*)(Q + (size_t)(q0 + r) * Dm + h * HDd + quad * 4);
        *(float4*)&Qs[r * 68 + quad * 4] = q4;
    }
    const int x = tid & 63;   // key index within tile / head-dim column
    const int y = tid >> 6;   // 0..3 -> query rows {y, y+4, y+8, y+12}
    __syncthreads();

    // Phase 1: scores = (Q K^T) * 1/sqrt(64), streamed K tiles of 64 keys
    for (int kt = 0; kt < nt; kt++) {
        int j0 = beg + kt * 64;
        for (int idx = tid; idx < 64 * 16; idx += 256) {
            int r = idx >> 4, quad = idx & 15;
            float4 k4 = make_float4(0.f, 0.f, 0.f, 0.f);
            if (j0 + r < end)
                k4 = *(const float4*)(K + (size_t)(j0 + r) * Dm + h * HDd + quad * 4);
            *(float4*)&Ks[r * 68 + quad * 4] = k4;
        }
        __syncthreads();

        float acc[4] = {0.f, 0.f, 0.f, 0.f};
#pragma unroll
        for (int dq = 0; dq < 16; dq++) {
            float4 k4 = *(const float4*)&Ks[x * 68 + dq * 4];
#pragma unroll
            for (int rr = 0; rr < 4; rr++) {
                int r = y + rr * 4;
                if (r < QG) {
                    float4 q4 = *(const float4*)&Qs[r * 68 + dq * 4];
                    acc[rr] += q4.x * k4.x + q4.y * k4.y + q4.z * k4.z + q4.w * k4.w;
                }
            }
        }
        bool valid = (j0 + x) < end;
#pragma unroll
        for (int rr = 0; rr < 4; rr++) {
            int r = y + rr * 4;
            if (r < QG)
                Ps[r * LMAX + kt * 64 + x] = valid ? acc[rr] * 0.125f : -1e30f;
        }
        __syncthreads();
    }

    // Phase 2: softmax per query row over [0, Lp) (pads are -1e30 -> exp 0)
    const int warp = tid >> 5, lane = tid & 31;
    for (int r = warp; r < QG; r += 8) {
        float* row = Ps + r * LMAX;
        float mval = -3e38f;
        for (int j = lane; j < Lp; j += 32) mval = fmaxf(mval, row[j]);
#pragma unroll
        for (int o = 16; o; o >>= 1) mval = fmaxf(mval, __shfl_xor_sync(0xffffffffu, mval, o));
        float ssum = 0.f;
        for (int j = lane; j < Lp; j += 32) {
            float e = __expf(row[j] - mval);
            row[j] = e;
            ssum += e;
        }
#pragma unroll
        for (int o = 16; o; o >>= 1) ssum += __shfl_xor_sync(0xffffffffu, ssum, o);
        float inv = 1.f / ssum;
        for (int j = lane; j < Lp; j += 32) row[j] *= inv;
    }
    __syncthreads();

    // Phase 3: O = P @ V, streamed V tiles (reusing Ks)
    float outr[4] = {0.f, 0.f, 0.f, 0.f};
    for (int kt = 0; kt < nt; kt++) {
        int j0 = beg + kt * 64;
        for (int idx = tid; idx < 64 * 16; idx += 256) {
            int r = idx >> 4, quad = idx & 15;
            float4 v4 = make_float4(0.f, 0.f, 0.f, 0.f);
            if (j0 + r < end)
                v4 = *(const float4*)(V + (size_t)(j0 + r) * Dm + h * HDd + quad * 4);
            *(float4*)&Ks[r * 68 + quad * 4] = v4;
        }
        __syncthreads();
#pragma unroll 8
        for (int kk = 0; kk < 64; kk++) {
            float v = Ks[kk * 68 + x];
#pragma unroll
            for (int rr = 0; rr < 4; rr++) {
                int r = y + rr * 4;
                if (r < QG)
                    outr[rr] += Ps[r * LMAX + kt * 64 + kk] * v;
            }
        }
        __syncthreads();
    }
#pragma unroll
    for (int rr = 0; rr < 4; rr++) {
        int r = y + rr * 4;
        if (r < QG)
            O[(size_t)(q0 + r) * Dm + h * HDd + x] = outr[rr];
    }
}

// ---------------------------------------------------------------------------
extern "C" void kernel_launch(void* const* d_in, const int* in_sizes, int n_in,
                              void* d_out, int out_size) {
    const float* xq  = (const float*)d_in[0];
    const float* xk  = (const float*)d_in[1];
    const float* pos = (const float*)d_in[2];
    const int*   ch  = (const int*)d_in[3];
    const float* Wq = (const float*)d_in[4];  const float* bq = (const float*)d_in[5];
    const float* Wk = (const float*)d_in[6];  const float* bk = (const float*)d_in[7];
    const float* Wv = (const float*)d_in[8];  const float* bv = (const float*)d_in[9];
    const float* Wo = (const float*)d_in[10]; const float* bo = (const float*)d_in[11];
    float* out = (float*)d_out;

    const int T = in_sizes[0] / Dm;       // 3136
    const int n_ch = in_sizes[3];         // 4

    void* p = nullptr;
    cudaGetSymbolAddress(&p, g_scratch);
    float* Q  = (float*)p;
    float* K  = Q + (size_t)MAXT * Dm;
    float* V  = K + (size_t)MAXT * Dm;
    float* Ob = V + (size_t)MAXT * Dm;
    void* ps = nullptr;
    cudaGetSymbolAddress(&ps, g_seg);
    int* segbeg = (int*)ps;
    int* segend = segbeg + MAXT;

    const int ATTN_SMEM = (QG * LMAX + QG * 68 + 64 * 68) * 4;  // ~93 KB
    cudaFuncSetAttribute(attn_kernel, cudaFuncAttributeMaxDynamicSharedMemorySize, ATTN_SMEM);

    setup_kernel<<<(T + 255) / 256, 256>>>(ch, n_ch, T, segbeg, segend);

    dim3 gg((T + BM - 1) / BM, Dm / BN);
    gemm_kernel<<<gg, 256>>>(xq, pos, Wq, bq, Q, T);
    gemm_kernel<<<gg, 256>>>(xk, pos, Wk, bk, K, T);
    gemm_kernel<<<gg, 256>>>(xk, nullptr, Wv, bv, V, T);

    dim3 ga((T + QG - 1) / QG, Hn);
    attn_kernel<<<ga, 256, ATTN_SMEM>>>(Q, K, V, Ob, segbeg, segend);

    gemm_kernel<<<gg, 256>>>(Ob, nullptr, Wo, bo, out, T);
}

// round 3
// speedup vs baseline: 1.2849x; 1.2849x over previous
#include <cuda_runtime.h>
#include <cuda_bf16.h>
#include <math.h>
#include <cstdint>

// Model constants (fixed by the problem).
#define Dm   512
#define Hn   8
#define HDd  64
#define Sg   196
#define MAXT 4096
#define QG   14      // queries per attention block; 14 | 196 so no segment straddle
#define LMAX 1280    // max padded segment length

// Scratch: Q, K, V, O_attn  (4 * 4096 * 512 fp32 = 32 MB) + segment bounds.
__device__ float g_scratch[4 * MAXT * Dm];
__device__ int   g_seg[2 * MAXT];

__device__ __forceinline__ uint32_t smem_u32(const void* p) {
    uint32_t a;
    asm("{ .reg .u64 t; cvta.to.shared.u64 t, %1; cvt.u32.u64 %0, t; }" : "=r"(a) : "l"(p));
    return a;
}
__device__ __forceinline__ void ldsm_x4(uint32_t* r, uint32_t addr) {
    asm volatile("ldmatrix.sync.aligned.m8n8.x4.shared.b16 {%0,%1,%2,%3}, [%4];"
                 : "=r"(r[0]), "=r"(r[1]), "=r"(r[2]), "=r"(r[3]) : "r"(addr));
}
__device__ __forceinline__ void mma_bf16(float* c, const uint32_t* a, uint32_t b0, uint32_t b1) {
    asm volatile("mma.sync.aligned.m16n8k16.row.col.f32.bf16.bf16.f32 "
                 "{%0,%1,%2,%3}, {%4,%5,%6,%7}, {%8,%9}, {%0,%1,%2,%3};"
                 : "+f"(c[0]), "+f"(c[1]), "+f"(c[2]), "+f"(c[3])
                 : "r"(a[0]), "r"(a[1]), "r"(a[2]), "r"(a[3]), "r"(b0), "r"(b1));
}
__device__ __forceinline__ uint32_t pack2(__nv_bfloat16 x, __nv_bfloat16 y) {
    __nv_bfloat162 t(x, y);
    return *(uint32_t*)&t;
}

// ---------------------------------------------------------------------------
// Segment setup
// ---------------------------------------------------------------------------
__global__ void setup_kernel(const int* __restrict__ channels, int n_ch, int T,
                             int* __restrict__ segbeg, int* __restrict__ segend) {
    int t = blockIdx.x * blockDim.x + threadIdx.x;
    if (t >= T) return;
    int beg = 0, end = 0;
    for (int i = 0; i < n_ch; i++) {
        int len = channels[i] * Sg;
        end = beg + len;
        if (t < end) break;
        beg = end;
    }
    segbeg[t] = beg;
    segend[t] = end;
}

// ---------------------------------------------------------------------------
// bf16 split-precision HMMA GEMM: C = (A (+A2)) @ W + bias
// 128x128 tile, k-chunk 32, warp tile 32x64, 3 products (AhBh+AhBl+AlBh).
// Smem pitch 40 bf16 (80B, 16B-aligned rows for ldmatrix).
// ---------------------------------------------------------------------------
#define GBM 128
#define GBN 128
#define GKC 32
#define PITCH 40

__global__ __launch_bounds__(256)
void gemm_mma(const float* __restrict__ A, const float* __restrict__ A2,
              const float* __restrict__ W, const float* __restrict__ bias,
              float* __restrict__ C, int M) {
    __shared__ __nv_bfloat16 As[2][GBM * PITCH];   // [hi/lo][m][k]
    __shared__ __nv_bfloat16 Bs[2][GBN * PITCH];   // [hi/lo][n][k]

    const int tid = threadIdx.x, wid = tid >> 5, lane = tid & 31;
    const int m0 = blockIdx.x * GBM, n0 = blockIdx.y * GBN;
    const int wm = (wid & 3) * 32;    // warp m-offset
    const int wn = (wid >> 2) * 64;   // warp n-offset

    const uint32_t sAhi = smem_u32(As[0]), sAlo = smem_u32(As[1]);
    const uint32_t sBhi = smem_u32(Bs[0]), sBlo = smem_u32(Bs[1]);

    float acc[2][8][4];
#pragma unroll
    for (int i = 0; i < 2; i++)
#pragma unroll
        for (int j = 0; j < 8; j++)
#pragma unroll
            for (int q = 0; q < 4; q++) acc[i][j][q] = 0.f;

    for (int c = 0; c < Dm / GKC; c++) {
        const int k0 = c * GKC;
        __syncthreads();   // protect previous chunk's reads

        // ---- A tile: 128 m x 32 k, hi/lo ----
#pragma unroll
        for (int i = 0; i < 4; i++) {
            int e = tid + i * 256;         // 1024 float4 groups
            int row = e >> 3, g = e & 7;
            int m = m0 + row;
            float4 a = make_float4(0.f, 0.f, 0.f, 0.f);
            if (m < M) {
                a = *(const float4*)(A + (size_t)m * Dm + k0 + g * 4);
                if (A2) {
                    float4 p = *(const float4*)(A2 + (size_t)m * Dm + k0 + g * 4);
                    a.x += p.x; a.y += p.y; a.z += p.z; a.w += p.w;
                }
            }
            __nv_bfloat16 h0 = __float2bfloat16(a.x), h1 = __float2bfloat16(a.y);
            __nv_bfloat16 h2 = __float2bfloat16(a.z), h3 = __float2bfloat16(a.w);
            __nv_bfloat16 l0 = __float2bfloat16(a.x - __bfloat162float(h0));
            __nv_bfloat16 l1 = __float2bfloat16(a.y - __bfloat162float(h1));
            __nv_bfloat16 l2 = __float2bfloat16(a.z - __bfloat162float(h2));
            __nv_bfloat16 l3 = __float2bfloat16(a.w - __bfloat162float(h3));
            int o = row * PITCH + g * 4;
            *(uint2*)&As[0][o] = make_uint2(pack2(h0, h1), pack2(h2, h3));
            *(uint2*)&As[1][o] = make_uint2(pack2(l0, l1), pack2(l2, l3));
        }
        // ---- B tile: W[k][n] -> Bs[n][k], hi/lo. One n per lane, 8 k per item.
#pragma unroll
        for (int i = 0; i < 2; i++) {
            int item = tid + i * 256;      // 512 items: n(128) x kb(4)
            int n = item & 127, kb = item >> 7;
            float v[8];
#pragma unroll
            for (int kk = 0; kk < 8; kk++)
                v[kk] = W[(size_t)(k0 + kb * 8 + kk) * Dm + n0 + n];
            uint32_t hi[4], lo[4];
#pragma unroll
            for (int q = 0; q < 4; q++) {
                __nv_bfloat16 ha = __float2bfloat16(v[q * 2 + 0]);
                __nv_bfloat16 hb = __float2bfloat16(v[q * 2 + 1]);
                __nv_bfloat16 la = __float2bfloat16(v[q * 2 + 0] - __bfloat162float(ha));
                __nv_bfloat16 lb = __float2bfloat16(v[q * 2 + 1] - __bfloat162float(hb));
                hi[q] = pack2(ha, hb);
                lo[q] = pack2(la, lb);
            }
            int o = n * PITCH + kb * 8;
            *(uint4*)&Bs[0][o] = make_uint4(hi[0], hi[1], hi[2], hi[3]);
            *(uint4*)&Bs[1][o] = make_uint4(lo[0], lo[1], lo[2], lo[3]);
        }
        __syncthreads();

        // ---- 3 products x 2 k16-steps ----
#pragma unroll
        for (int prod = 0; prod < 3; prod++) {
            const uint32_t sA = (prod == 2) ? sAlo : sAhi;
            const uint32_t sB = (prod == 1) ? sBlo : sBhi;
#pragma unroll
            for (int ks = 0; ks < 2; ks++) {
                uint32_t a[2][4];
#pragma unroll
                for (int im = 0; im < 2; im++) {
                    uint32_t addr = sA + 2 * ((wm + im * 16 + (lane & 15)) * PITCH +
                                              ks * 16 + (lane >> 4) * 8);
                    ldsm_x4(a[im], addr);
                }
                uint32_t b[4][4];
#pragma unroll
                for (int ib = 0; ib < 4; ib++) {
                    int n = wn + ib * 16 + ((lane >> 4) * 8) + (lane & 7);
                    uint32_t addr = sB + 2 * (n * PITCH + ks * 16 + ((lane >> 3) & 1) * 8);
                    ldsm_x4(b[ib], addr);
                }
#pragma unroll
                for (int im = 0; im < 2; im++)
#pragma unroll
                    for (int ib = 0; ib < 4; ib++) {
                        mma_bf16(acc[im][ib * 2 + 0], a[im], b[ib][0], b[ib][1]);
                        mma_bf16(acc[im][ib * 2 + 1], a[im], b[ib][2], b[ib][3]);
                    }
            }
        }
    }

    // ---- Epilogue: acc + bias -> C ----
#pragma unroll
    for (int im = 0; im < 2; im++) {
        int r0 = m0 + wm + im * 16 + (lane >> 2);
#pragma unroll
        for (int ib = 0; ib < 8; ib++) {
            int col = n0 + wn + ib * 8 + (lane & 3) * 2;
            float2 bv = *(const float2*)(bias + col);
            if (r0 < M) {
                float2 o0;
                o0.x = acc[im][ib][0] + bv.x;
                o0.y = acc[im][ib][1] + bv.y;
                *(float2*)(C + (size_t)r0 * Dm + col) = o0;
            }
            if (r0 + 8 < M) {
                float2 o1;
                o1.x = acc[im][ib][2] + bv.x;
                o1.y = acc[im][ib][3] + bv.y;
                *(float2*)(C + (size_t)(r0 + 8) * Dm + col) = o1;
            }
        }
    }
}

// ---------------------------------------------------------------------------
// Fused attention (unchanged, known-good): block = (14-query group, head).
// ---------------------------------------------------------------------------
__global__ __launch_bounds__(256)
void attn_kernel(const float* __restrict__ Q, const float* __restrict__ K,
                 const float* __restrict__ V, float* __restrict__ O,
                 const int* __restrict__ segbeg, const int* __restrict__ segend) {
    extern __shared__ float sm[];
    float* Ps = sm;                      // [QG][LMAX] scores
    float* Qs = Ps + QG * LMAX;          // [QG][68]
    float* Ks = Qs + QG * 68;            // [64][68]  (reused for V)

    const int q0 = blockIdx.x * QG;
    const int h  = blockIdx.y;
    const int tid = threadIdx.x;
    const int beg = segbeg[q0];
    const int end = segend[q0];
    const int nt = (end - beg + 63) >> 6;
    const int Lp = nt << 6;

    for (int idx = tid; idx < QG * 16; idx += 256) {
        int r = idx >> 4, quad = idx & 15;
        float4 q4 = *(const float4*)(Q + (size_t)(q0 + r) * Dm + h * HDd + quad * 4);
        *(float4*)&Qs[r * 68 + quad * 4] = q4;
    }
    const int x = tid & 63;
    const int y = tid >> 6;
    __syncthreads();

    for (int kt = 0; kt < nt; kt++) {
        int j0 = beg + kt * 64;
        for (int idx = tid; idx < 64 * 16; idx += 256) {
            int r = idx >> 4, quad = idx & 15;
            float4 k4 = make_float4(0.f, 0.f, 0.f, 0.f);
            if (j0 + r < end)
                k4 = *(const float4*)(K + (size_t)(j0 + r) * Dm + h * HDd + quad * 4);
            *(float4*)&Ks[r * 68 + quad * 4] = k4;
        }
        __syncthreads();

        float acc[4] = {0.f, 0.f, 0.f, 0.f};
#pragma unroll
        for (int dq = 0; dq < 16; dq++) {
            float4 k4 = *(const float4*)&Ks[x * 68 + dq * 4];
#pragma unroll
            for (int rr = 0; rr < 4; rr++) {
                int r = y + rr * 4;
                if (r < QG) {
                    float4 q4 = *(const float4*)&Qs[r * 68 + dq * 4];
                    acc[rr] += q4.x * k4.x + q4.y * k4.y + q4.z * k4.z + q4.w * k4.w;
                }
            }
        }
        bool valid = (j0 + x) < end;
#pragma unroll
        for (int rr = 0; rr < 4; rr++) {
            int r = y + rr * 4;
            if (r < QG)
                Ps[r * LMAX + kt * 64 + x] = valid ? acc[rr] * 0.125f : -1e30f;
        }
        __syncthreads();
    }

    const int warp = tid >> 5, lane = tid & 31;
    for (int r = warp; r < QG; r += 8) {
        float* row = Ps + r * LMAX;
        float mval = -3e38f;
        for (int j = lane; j < Lp; j += 32) mval = fmaxf(mval, row[j]);
#pragma unroll
        for (int o = 16; o; o >>= 1) mval = fmaxf(mval, __shfl_xor_sync(0xffffffffu, mval, o));
        float ssum = 0.f;
        for (int j = lane; j < Lp; j += 32) {
            float e = __expf(row[j] - mval);
            row[j] = e;
            ssum += e;
        }
#pragma unroll
        for (int o = 16; o; o >>= 1) ssum += __shfl_xor_sync(0xffffffffu, ssum, o);
        float inv = 1.f / ssum;
        for (int j = lane; j < Lp; j += 32) row[j] *= inv;
    }
    __syncthreads();

    float outr[4] = {0.f, 0.f, 0.f, 0.f};
    for (int kt = 0; kt < nt; kt++) {
        int j0 = beg + kt * 64;
        for (int idx = tid; idx < 64 * 16; idx += 256) {
            int r = idx >> 4, quad = idx & 15;
            float4 v4 = make_float4(0.f, 0.f, 0.f, 0.f);
            if (j0 + r < end)
                v4 = *(const float4*)(V + (size_t)(j0 + r) * Dm + h * HDd + quad * 4);
            *(float4*)&Ks[r * 68 + quad * 4] = v4;
        }
        __syncthreads();
#pragma unroll 8
        for (int kk = 0; kk < 64; kk++) {
            float v = Ks[kk * 68 + x];
#pragma unroll
            for (int rr = 0; rr < 4; rr++) {
                int r = y + rr * 4;
                if (r < QG)
                    outr[rr] += Ps[r * LMAX + kt * 64 + kk] * v;
            }
        }
        __syncthreads();
    }
#pragma unroll
    for (int rr = 0; rr < 4; rr++) {
        int r = y + rr * 4;
        if (r < QG)
            O[(size_t)(q0 + r) * Dm + h * HDd + x] = outr[rr];
    }
}

// ---------------------------------------------------------------------------
extern "C" void kernel_launch(void* const* d_in, const int* in_sizes, int n_in,
                              void* d_out, int out_size) {
    const float* xq  = (const float*)d_in[0];
    const float* xk  = (const float*)d_in[1];
    const float* pos = (const float*)d_in[2];
    const int*   ch  = (const int*)d_in[3];
    const float* Wq = (const float*)d_in[4];  const float* bq = (const float*)d_in[5];
    const float* Wk = (const float*)d_in[6];  const float* bk = (const float*)d_in[7];
    const float* Wv = (const float*)d_in[8];  const float* bv = (const float*)d_in[9];
    const float* Wo = (const float*)d_in[10]; const float* bo = (const float*)d_in[11];
    float* out = (float*)d_out;

    const int T = in_sizes[0] / Dm;       // 3136
    const int n_ch = in_sizes[3];         // 4

    void* p = nullptr;
    cudaGetSymbolAddress(&p, g_scratch);
    float* Q  = (float*)p;
    float* K  = Q + (size_t)MAXT * Dm;
    float* V  = K + (size_t)MAXT * Dm;
    float* Ob = V + (size_t)MAXT * Dm;
    void* ps = nullptr;
    cudaGetSymbolAddress(&ps, g_seg);
    int* segbeg = (int*)ps;
    int* segend = segbeg + MAXT;

    const int ATTN_SMEM = (QG * LMAX + QG * 68 + 64 * 68) * 4;  // ~93 KB
    cudaFuncSetAttribute(attn_kernel, cudaFuncAttributeMaxDynamicSharedMemorySize, ATTN_SMEM);

    setup_kernel<<<(T + 255) / 256, 256>>>(ch, n_ch, T, segbeg, segend);

    dim3 gg((T + GBM - 1) / GBM, Dm / GBN);
    gemm_mma<<<gg, 256>>>(xq, pos, Wq, bq, Q, T);
    gemm_mma<<<gg, 256>>>(xk, pos, Wk, bk, K, T);
    gemm_mma<<<gg, 256>>>(xk, nullptr, Wv, bv, V, T);

    dim3 ga((T + QG - 1) / QG, Hn);
    attn_kernel<<<ga, 256, ATTN_SMEM>>>(Q, K, V, Ob, segbeg, segend);

    gemm_mma<<<gg, 256>>>(Ob, nullptr, Wo, bo, out, T);
}

// round 5
// speedup vs baseline: 1.3040x; 1.0149x over previous
#include <cuda_runtime.h>
#include <cuda_bf16.h>
#include <math.h>
#include <cstdint>

// Model constants (fixed by the problem).
#define Dm   512
#define Hn   8
#define HDd  64
#define Sg   196
#define MAXT 4096
#define QG   14      // queries per attention block; 14 | 196 so no segment straddle
#define TK   128     // keys per attention tile
#define PS   1284    // score strip pitch (floats), LMAX=1280 + 4 pad
#define KP   72      // K/V smem pitch (bf16)
#define PP   136     // P smem pitch (bf16)

// Scratch: Ob fp32 (8MB) + 6 bf16 arrays (Qhi,Qlo,Khi,Klo,Vhi,Vlo; 24MB) = 32MB.
__device__ float g_scratch[4 * MAXT * Dm];
__device__ int   g_seg[2 * MAXT];

__device__ __forceinline__ uint32_t smem_u32(const void* p) {
    uint32_t a;
    asm("{ .reg .u64 t; cvta.to.shared.u64 t, %1; cvt.u32.u64 %0, t; }" : "=r"(a) : "l"(p));
    return a;
}
__device__ __forceinline__ void ldsm_x4(uint32_t* r, uint32_t addr) {
    asm volatile("ldmatrix.sync.aligned.m8n8.x4.shared.b16 {%0,%1,%2,%3}, [%4];"
                 : "=r"(r[0]), "=r"(r[1]), "=r"(r[2]), "=r"(r[3]) : "r"(addr));
}
__device__ __forceinline__ void ldsm_x2_t(uint32_t* r, uint32_t addr) {
    asm volatile("ldmatrix.sync.aligned.m8n8.x2.trans.shared.b16 {%0,%1}, [%2];"
                 : "=r"(r[0]), "=r"(r[1]) : "r"(addr));
}
__device__ __forceinline__ void mma_bf16(float* c, const uint32_t* a, uint32_t b0, uint32_t b1) {
    asm volatile("mma.sync.aligned.m16n8k16.row.col.f32.bf16.bf16.f32 "
                 "{%0,%1,%2,%3}, {%4,%5,%6,%7}, {%8,%9}, {%0,%1,%2,%3};"
                 : "+f"(c[0]), "+f"(c[1]), "+f"(c[2]), "+f"(c[3])
                 : "r"(a[0]), "r"(a[1]), "r"(a[2]), "r"(a[3]), "r"(b0), "r"(b1));
}
__device__ __forceinline__ uint32_t pack2(__nv_bfloat16 x, __nv_bfloat16 y) {
    __nv_bfloat162 t(x, y);
    return *(uint32_t*)&t;
}

// ---------------------------------------------------------------------------
// Segment setup
// ---------------------------------------------------------------------------
__global__ void setup_kernel(const int* __restrict__ channels, int n_ch, int T,
                             int* __restrict__ segbeg, int* __restrict__ segend) {
    int t = blockIdx.x * blockDim.x + threadIdx.x;
    if (t >= T) return;
    int beg = 0, end = 0;
    for (int i = 0; i < n_ch; i++) {
        int len = channels[i] * Sg;
        end = beg + len;
        if (t < end) break;
        beg = end;
    }
    segbeg[t] = beg;
    segend[t] = end;
}

// ---------------------------------------------------------------------------
// bf16 split-precision HMMA GEMM: C = (A (+A2)) @ W + bias
// 128x64 tile, k-chunk 32, warp tile 32x32, 3 products (AhBh+AhBl+AlBh).
// Optional outputs: fp32 C, and/or bf16 hi/lo pair.
// ---------------------------------------------------------------------------
#define GBM 128
#define GBN 64
#define GKC 32
#define PITCH 40

__global__ __launch_bounds__(256)
void gemm_mma(const float* __restrict__ A, const float* __restrict__ A2,
              const float* __restrict__ W, const float* __restrict__ bias,
              float* __restrict__ Cf, __nv_bfloat16* __restrict__ Chi,
              __nv_bfloat16* __restrict__ Clo, int M) {
    __shared__ __nv_bfloat16 As[2][GBM * PITCH];   // [hi/lo][m][k]
    __shared__ __nv_bfloat16 Bs[2][GBN * PITCH];   // [hi/lo][n][k]

    const int tid = threadIdx.x, wid = tid >> 5, lane = tid & 31;
    const int m0 = blockIdx.x * GBM, n0 = blockIdx.y * GBN;
    const int wm = (wid & 3) * 32;    // warp m-offset
    const int wn = (wid >> 2) * 32;   // warp n-offset

    const uint32_t sAhi = smem_u32(As[0]), sAlo = smem_u32(As[1]);
    const uint32_t sBhi = smem_u32(Bs[0]), sBlo = smem_u32(Bs[1]);

    float acc[2][4][4];
#pragma unroll
    for (int i = 0; i < 2; i++)
#pragma unroll
        for (int j = 0; j < 4; j++)
#pragma unroll
            for (int q = 0; q < 4; q++) acc[i][j][q] = 0.f;

    for (int c = 0; c < Dm / GKC; c++) {
        const int k0 = c * GKC;
        __syncthreads();

        // ---- A tile: 128 m x 32 k, hi/lo ----
#pragma unroll
        for (int i = 0; i < 4; i++) {
            int e = tid + i * 256;         // 1024 float4 groups
            int row = e >> 3, g = e & 7;
            int m = m0 + row;
            float4 a = make_float4(0.f, 0.f, 0.f, 0.f);
            if (m < M) {
                a = *(const float4*)(A + (size_t)m * Dm + k0 + g * 4);
                if (A2) {
                    float4 p = *(const float4*)(A2 + (size_t)m * Dm + k0 + g * 4);
                    a.x += p.x; a.y += p.y; a.z += p.z; a.w += p.w;
                }
            }
            __nv_bfloat16 h0 = __float2bfloat16(a.x), h1 = __float2bfloat16(a.y);
            __nv_bfloat16 h2 = __float2bfloat16(a.z), h3 = __float2bfloat16(a.w);
            __nv_bfloat16 l0 = __float2bfloat16(a.x - __bfloat162float(h0));
            __nv_bfloat16 l1 = __float2bfloat16(a.y - __bfloat162float(h1));
            __nv_bfloat16 l2 = __float2bfloat16(a.z - __bfloat162float(h2));
            __nv_bfloat16 l3 = __float2bfloat16(a.w - __bfloat162float(h3));
            int o = row * PITCH + g * 4;
            *(uint2*)&As[0][o] = make_uint2(pack2(h0, h1), pack2(h2, h3));
            *(uint2*)&As[1][o] = make_uint2(pack2(l0, l1), pack2(l2, l3));
        }
        // ---- B tile: W[k][n] -> Bs[n][k], hi/lo. 256 items = 64 n x 4 kb.
        {
            int n = tid & 63, kb = tid >> 6;
            float v[8];
#pragma unroll
            for (int kk = 0; kk < 8; kk++)
                v[kk] = W[(size_t)(k0 + kb * 8 + kk) * Dm + n0 + n];
            uint32_t hi[4], lo[4];
#pragma unroll
            for (int q = 0; q < 4; q++) {
                __nv_bfloat16 ha = __float2bfloat16(v[q * 2 + 0]);
                __nv_bfloat16 hb = __float2bfloat16(v[q * 2 + 1]);
                __nv_bfloat16 la = __float2bfloat16(v[q * 2 + 0] - __bfloat162float(ha));
                __nv_bfloat16 lb = __float2bfloat16(v[q * 2 + 1] - __bfloat162float(hb));
                hi[q] = pack2(ha, hb);
                lo[q] = pack2(la, lb);
            }
            int o = n * PITCH + kb * 8;
            *(uint4*)&Bs[0][o] = make_uint4(hi[0], hi[1], hi[2], hi[3]);
            *(uint4*)&Bs[1][o] = make_uint4(lo[0], lo[1], lo[2], lo[3]);
        }
        __syncthreads();

#pragma unroll
        for (int prod = 0; prod < 3; prod++) {
            const uint32_t sA = (prod == 2) ? sAlo : sAhi;
            const uint32_t sB = (prod == 1) ? sBlo : sBhi;
#pragma unroll
            for (int ks = 0; ks < 2; ks++) {
                uint32_t a[2][4];
#pragma unroll
                for (int im = 0; im < 2; im++) {
                    uint32_t addr = sA + 2 * ((wm + im * 16 + (lane & 15)) * PITCH +
                                              ks * 16 + (lane >> 4) * 8);
                    ldsm_x4(a[im], addr);
                }
                uint32_t b[2][4];
#pragma unroll
                for (int ib = 0; ib < 2; ib++) {
                    int n = wn + ib * 16 + ((lane >> 4) * 8) + (lane & 7);
                    uint32_t addr = sB + 2 * (n * PITCH + ks * 16 + ((lane >> 3) & 1) * 8);
                    ldsm_x4(b[ib], addr);
                }
#pragma unroll
                for (int im = 0; im < 2; im++)
#pragma unroll
                    for (int ib = 0; ib < 2; ib++) {
                        mma_bf16(acc[im][ib * 2 + 0], a[im], b[ib][0], b[ib][1]);
                        mma_bf16(acc[im][ib * 2 + 1], a[im], b[ib][2], b[ib][3]);
                    }
            }
        }
    }

    // ---- Epilogue: acc + bias -> fp32 and/or bf16 hi/lo ----
#pragma unroll
    for (int im = 0; im < 2; im++) {
#pragma unroll
        for (int ib = 0; ib < 4; ib++) {
            int col = n0 + wn + ib * 8 + (lane & 3) * 2;
            float2 bv = *(const float2*)(bias + col);
#pragma unroll
            for (int hf = 0; hf < 2; hf++) {
                int r = m0 + wm + im * 16 + (lane >> 2) + hf * 8;
                if (r >= M) continue;
                float ox = acc[im][ib][hf * 2 + 0] + bv.x;
                float oy = acc[im][ib][hf * 2 + 1] + bv.y;
                if (Cf)
                    *(float2*)(Cf + (size_t)r * Dm + col) = make_float2(ox, oy);
                if (Chi) {
                    __nv_bfloat16 hx = __float2bfloat16(ox), hy = __float2bfloat16(oy);
                    __nv_bfloat16 lx = __float2bfloat16(ox - __bfloat162float(hx));
                    __nv_bfloat16 ly = __float2bfloat16(oy - __bfloat162float(hy));
                    *(uint32_t*)(Chi + (size_t)r * Dm + col) = pack2(hx, hy);
                    *(uint32_t*)(Clo + (size_t)r * Dm + col) = pack2(lx, ly);
                }
            }
        }
    }
}

// ---------------------------------------------------------------------------
// Tensor-core attention: block = (14-query group padded to m16, head).
// Phase1: scores strip via split-precision mma; Phase2: exact softmax;
// Phase3: P@V via mma with trans-ldmatrix for V.
// ---------------------------------------------------------------------------
// smem byte offsets
#define SM_STRIP 0
#define SM_KTH   82176
#define SM_KTL   100608
#define SM_QBH   119040
#define SM_QBL   121344
#define SM_PBH   123648
#define SM_PBL   128000
#define SM_INV   132352
#define ATTN_SMEM 132416

__global__ __launch_bounds__(256)
void attn_mma(const __nv_bfloat16* __restrict__ Qhi, const __nv_bfloat16* __restrict__ Qlo,
              const __nv_bfloat16* __restrict__ Khi, const __nv_bfloat16* __restrict__ Klo,
              const __nv_bfloat16* __restrict__ Vhi, const __nv_bfloat16* __restrict__ Vlo,
              float* __restrict__ O, const int* __restrict__ segbeg,
              const int* __restrict__ segend) {
    extern __shared__ char sm[];
    float* strip = (float*)(sm + SM_STRIP);            // [16][PS]
    __nv_bfloat16* Kth = (__nv_bfloat16*)(sm + SM_KTH); // [128][KP]
    __nv_bfloat16* Ktl = (__nv_bfloat16*)(sm + SM_KTL);
    __nv_bfloat16* Qbh = (__nv_bfloat16*)(sm + SM_QBH); // [16][KP]
    __nv_bfloat16* Qbl = (__nv_bfloat16*)(sm + SM_QBL);
    __nv_bfloat16* Pbh = (__nv_bfloat16*)(sm + SM_PBH); // [16][PP]
    __nv_bfloat16* Pbl = (__nv_bfloat16*)(sm + SM_PBL);
    float* invs = (float*)(sm + SM_INV);
    const uint32_t sKh = smem_u32(Kth), sKl = smem_u32(Ktl);
    const uint32_t sQh = smem_u32(Qbh), sQl = smem_u32(Qbl);
    const uint32_t sPh = smem_u32(Pbh), sPl = smem_u32(Pbl);

    const int q0 = blockIdx.x * QG;
    const int h = blockIdx.y;
    const int tid = threadIdx.x, wid = tid >> 5, lane = tid & 31;
    const int beg = segbeg[q0], end = segend[q0];
    const int nt = (end - beg + TK - 1) / TK;

    // ---- Q tile [16][64] bf16 hi/lo (rows >= QG zeroed) ----
    if (tid < 128) {
        int row = tid >> 3, g = tid & 7;
        uint4 h4 = make_uint4(0, 0, 0, 0), l4 = make_uint4(0, 0, 0, 0);
        if (row < QG) {
            h4 = *(const uint4*)(Qhi + (size_t)(q0 + row) * Dm + h * HDd + g * 8);
            l4 = *(const uint4*)(Qlo + (size_t)(q0 + row) * Dm + h * HDd + g * 8);
        }
        *(uint4*)&Qbh[row * KP + g * 8] = h4;
        *(uint4*)&Qbl[row * KP + g * 8] = l4;
    }
    __syncthreads();
    uint32_t qh[4][4], ql[4][4];
#pragma unroll
    for (int ks = 0; ks < 4; ks++) {
        uint32_t ar = 2 * ((lane & 15) * KP + ks * 16 + (lane >> 4) * 8);
        ldsm_x4(qh[ks], sQh + ar);
        ldsm_x4(ql[ks], sQl + ar);
    }

    // ---- Phase 1: score strip ----
    for (int kt = 0; kt < nt; kt++) {
        int j0 = beg + kt * TK;
        __syncthreads();
#pragma unroll
        for (int i = 0; i < 4; i++) {
            int idx = tid + i * 256;        // 1024 = 128 rows x 8 groups
            int row = idx >> 3, g = idx & 7;
            int key = j0 + row;
            uint4 h4 = make_uint4(0, 0, 0, 0), l4 = make_uint4(0, 0, 0, 0);
            if (key < end) {
                h4 = *(const uint4*)(Khi + (size_t)key * Dm + h * HDd + g * 8);
                l4 = *(const uint4*)(Klo + (size_t)key * Dm + h * HDd + g * 8);
            }
            *(uint4*)&Kth[row * KP + g * 8] = h4;
            *(uint4*)&Ktl[row * KP + g * 8] = l4;
        }
        __syncthreads();

        float c[2][4] = {{0.f, 0.f, 0.f, 0.f}, {0.f, 0.f, 0.f, 0.f}};
#pragma unroll
        for (int ks = 0; ks < 4; ks++) {
            uint32_t br = 2 * ((wid * 16 + (lane >> 4) * 8 + (lane & 7)) * KP +
                               ks * 16 + ((lane >> 3) & 1) * 8);
            uint32_t bh[4], bl[4];
            ldsm_x4(bh, sKh + br);
            ldsm_x4(bl, sKl + br);
            mma_bf16(c[0], qh[ks], bh[0], bh[1]);
            mma_bf16(c[0], qh[ks], bl[0], bl[1]);
            mma_bf16(c[0], ql[ks], bh[0], bh[1]);
            mma_bf16(c[1], qh[ks], bh[2], bh[3]);
            mma_bf16(c[1], qh[ks], bl[2], bl[3]);
            mma_bf16(c[1], ql[ks], bh[2], bh[3]);
        }
#pragma unroll
        for (int ch = 0; ch < 2; ch++) {
            int kb = wid * 16 + ch * 8 + (lane & 3) * 2;
            int col = kt * TK + kb;
            int key = j0 + kb;
#pragma unroll
            for (int hf = 0; hf < 2; hf++) {
                int row = (lane >> 2) + hf * 8;
                strip[row * PS + col]     = (key < end)     ? c[ch][hf * 2 + 0] * 0.125f : -1e30f;
                strip[row * PS + col + 1] = (key + 1 < end) ? c[ch][hf * 2 + 1] * 0.125f : -1e30f;
            }
        }
    }
    __syncthreads();

    // ---- Phase 2: softmax (exp stored in strip, inv-sum saved) ----
    const int Lp = nt * TK;
    for (int r = wid; r < QG; r += 8) {
        float* row = strip + r * PS;
        float m = -3e38f;
        for (int j = lane; j < Lp; j += 32) m = fmaxf(m, row[j]);
#pragma unroll
        for (int o = 16; o; o >>= 1) m = fmaxf(m, __shfl_xor_sync(0xffffffffu, m, o));
        float s = 0.f;
        for (int j = lane; j < Lp; j += 32) {
            float e = __expf(row[j] - m);
            row[j] = e;
            s += e;
        }
#pragma unroll
        for (int o = 16; o; o >>= 1) s += __shfl_xor_sync(0xffffffffu, s, o);
        if (lane == 0) invs[r] = 1.f / s;
    }
    __syncthreads();

    // ---- Phase 3: O = P @ V ----
    float o[4] = {0.f, 0.f, 0.f, 0.f};
    for (int kt = 0; kt < nt; kt++) {
        int j0 = beg + kt * TK;
        __syncthreads();
        // V tile (reuse K buffers)
#pragma unroll
        for (int i = 0; i < 4; i++) {
            int idx = tid + i * 256;
            int row = idx >> 3, g = idx & 7;
            int key = j0 + row;
            uint4 h4 = make_uint4(0, 0, 0, 0), l4 = make_uint4(0, 0, 0, 0);
            if (key < end) {
                h4 = *(const uint4*)(Vhi + (size_t)key * Dm + h * HDd + g * 8);
                l4 = *(const uint4*)(Vlo + (size_t)key * Dm + h * HDd + g * 8);
            }
            *(uint4*)&Kth[row * KP + g * 8] = h4;
            *(uint4*)&Ktl[row * KP + g * 8] = l4;
        }
        // P chunk [16][128] -> bf16 hi/lo (normalized)
#pragma unroll
        for (int i = 0; i < 4; i++) {
            int idx = tid + i * 256;        // 1024 = 16 rows x 64 col-pairs
            int row = idx >> 6, cp = (idx & 63) * 2;
            float p0 = 0.f, p1 = 0.f;
            if (row < QG) {
                float iv = invs[row];
                p0 = strip[row * PS + kt * TK + cp] * iv;
                p1 = strip[row * PS + kt * TK + cp + 1] * iv;
            }
            __nv_bfloat16 h0 = __float2bfloat16(p0), h1 = __float2bfloat16(p1);
            __nv_bfloat16 l0 = __float2bfloat16(p0 - __bfloat162float(h0));
            __nv_bfloat16 l1 = __float2bfloat16(p1 - __bfloat162float(h1));
            *(uint32_t*)&Pbh[row * PP + cp] = pack2(h0, h1);
            *(uint32_t*)&Pbl[row * PP + cp] = pack2(l0, l1);
        }
        __syncthreads();
#pragma unroll
        for (int ks = 0; ks < 8; ks++) {
            uint32_t ar = 2 * ((lane & 15) * PP + ks * 16 + (lane >> 4) * 8);
            uint32_t ah[4], al[4];
            ldsm_x4(ah, sPh + ar);
            ldsm_x4(al, sPl + ar);
            uint32_t vr = 2 * ((ks * 16 + (lane & 15)) * KP + wid * 8);
            uint32_t bh[2], bl[2];
            ldsm_x2_t(bh, sKh + vr);
            ldsm_x2_t(bl, sKl + vr);
            mma_bf16(o, ah, bh[0], bh[1]);
            mma_bf16(o, ah, bl[0], bl[1]);
            mma_bf16(o, al, bh[0], bh[1]);
        }
    }

    // ---- Write O ----
    int col = h * HDd + wid * 8 + (lane & 3) * 2;
    int r0 = lane >> 2;
    if (r0 < QG)
        *(float2*)(O + (size_t)(q0 + r0) * Dm + col) = make_float2(o[0], o[1]);
    if (r0 + 8 < QG)
        *(float2*)(O + (size_t)(q0 + r0 + 8) * Dm + col) = make_float2(o[2], o[3]);
}

// ---------------------------------------------------------------------------
extern "C" void kernel_launch(void* const* d_in, const int* in_sizes, int n_in,
                              void* d_out, int out_size) {
    const float* xq  = (const float*)d_in[0];
    const float* xk  = (const float*)d_in[1];
    const float* pos = (const float*)d_in[2];
    const int*   ch  = (const int*)d_in[3];
    const float* Wq = (const float*)d_in[4];  const float* bq = (const float*)d_in[5];
    const float* Wk = (const float*)d_in[6];  const float* bk = (const float*)d_in[7];
    const float* Wv = (const float*)d_in[8];  const float* bv = (const float*)d_in[9];
    const float* Wo = (const float*)d_in[10]; const float* bo = (const float*)d_in[11];
    float* out = (float*)d_out;

    const int T = in_sizes[0] / Dm;       // 3136
    const int n_ch = in_sizes[3];         // 4

    void* p = nullptr;
    cudaGetSymbolAddress(&p, g_scratch);
    float* scr = (float*)p;
    const size_t SZ = (size_t)MAXT * Dm;
    float* Ob = scr;                                     // fp32 [MAXT][Dm]
    __nv_bfloat16* b16 = (__nv_bfloat16*)(scr + SZ);
    __nv_bfloat16* Qhi = b16 + 0 * SZ;
    __nv_bfloat16* Qlo = b16 + 1 * SZ;
    __nv_bfloat16* Khi = b16 + 2 * SZ;
    __nv_bfloat16* Klo = b16 + 3 * SZ;
    __nv_bfloat16* Vhi = b16 + 4 * SZ;
    __nv_bfloat16* Vlo = b16 + 5 * SZ;

    void* ps = nullptr;
    cudaGetSymbolAddress(&ps, g_seg);
    int* segbeg = (int*)ps;
    int* segend = segbeg + MAXT;

    cudaFuncSetAttribute(attn_mma, cudaFuncAttributeMaxDynamicSharedMemorySize, ATTN_SMEM);

    setup_kernel<<<(T + 255) / 256, 256>>>(ch, n_ch, T, segbeg, segend);

    dim3 gg((T + GBM - 1) / GBM, Dm / GBN);
    gemm_mma<<<gg, 256>>>(xq, pos,     Wq, bq, nullptr, Qhi, Qlo, T);
    gemm_mma<<<gg, 256>>>(xk, pos,     Wk, bk, nullptr, Khi, Klo, T);
    gemm_mma<<<gg, 256>>>(xk, nullptr, Wv, bv, nullptr, Vhi, Vlo, T);

    dim3 ga((T + QG - 1) / QG, Hn);
    attn_mma<<<ga, 256, ATTN_SMEM>>>(Qhi, Qlo, Khi, Klo, Vhi, Vlo, Ob, segbeg, segend);

    gemm_mma<<<gg, 256>>>(Ob, nullptr, Wo, bo, out, nullptr, nullptr, T);
}

// round 6
// speedup vs baseline: 1.9709x; 1.5114x over previous
#include <cuda_runtime.h>
#include <cuda_bf16.h>
#include <math.h>
#include <cstdint>

#define Dm   512
#define Hn   8
#define HDd  64
#define Sg   196
#define MAXT 4096
#define QT   128     // queries per flash block
#define KT   64      // keys per flash tile
#define KP   72      // smem pitch (bf16) for K/V/Q tiles

// Scratch: Ob fp32 (8MB) + 6 bf16 arrays (Qhi,Qlo,Khi,Klo,Vhi,Vlo; 24MB) = 32MB.
__device__ float g_scratch[4 * MAXT * Dm];
__device__ int   g_sched[4 * MAXT];

__device__ __forceinline__ uint32_t smem_u32(const void* p) {
    uint32_t a;
    asm("{ .reg .u64 t; cvta.to.shared.u64 t, %1; cvt.u32.u64 %0, t; }" : "=r"(a) : "l"(p));
    return a;
}
__device__ __forceinline__ void ldsm_x4(uint32_t* r, uint32_t addr) {
    asm volatile("ldmatrix.sync.aligned.m8n8.x4.shared.b16 {%0,%1,%2,%3}, [%4];"
                 : "=r"(r[0]), "=r"(r[1]), "=r"(r[2]), "=r"(r[3]) : "r"(addr));
}
__device__ __forceinline__ void ldsm_x4_t(uint32_t* r, uint32_t addr) {
    asm volatile("ldmatrix.sync.aligned.m8n8.x4.trans.shared.b16 {%0,%1,%2,%3}, [%4];"
                 : "=r"(r[0]), "=r"(r[1]), "=r"(r[2]), "=r"(r[3]) : "r"(addr));
}
__device__ __forceinline__ void mma_bf16(float* c, const uint32_t* a, uint32_t b0, uint32_t b1) {
    asm volatile("mma.sync.aligned.m16n8k16.row.col.f32.bf16.bf16.f32 "
                 "{%0,%1,%2,%3}, {%4,%5,%6,%7}, {%8,%9}, {%0,%1,%2,%3};"
                 : "+f"(c[0]), "+f"(c[1]), "+f"(c[2]), "+f"(c[3])
                 : "r"(a[0]), "r"(a[1]), "r"(a[2]), "r"(a[3]), "r"(b0), "r"(b1));
}
__device__ __forceinline__ uint32_t pack2(__nv_bfloat16 x, __nv_bfloat16 y) {
    __nv_bfloat162 t(x, y);
    return *(uint32_t*)&t;
}
__device__ __forceinline__ void split2(float x, float y, uint32_t& hi, uint32_t& lo) {
    __nv_bfloat16 hx = __float2bfloat16(x), hy = __float2bfloat16(y);
    __nv_bfloat16 lx = __float2bfloat16(x - __bfloat162float(hx));
    __nv_bfloat16 ly = __float2bfloat16(y - __bfloat162float(hy));
    hi = pack2(hx, hy);
    lo = pack2(lx, ly);
}

// ---------------------------------------------------------------------------
// Schedule: per-segment q-tiles of QT. Entry: {q0, qlen, beg, end}.
// ---------------------------------------------------------------------------
__global__ void setup_sched(const int* __restrict__ channels, int n_ch,
                            int* __restrict__ sched) {
    if (threadIdx.x != 0 || blockIdx.x != 0) return;
    int cnt = 0, beg = 0;
    for (int i = 0; i < n_ch; i++) {
        int len = channels[i] * Sg, end = beg + len;
        for (int j = 0; j < len; j += QT) {
            sched[1 + cnt * 4 + 0] = beg + j;
            sched[1 + cnt * 4 + 1] = (len - j < QT) ? (len - j) : QT;
            sched[1 + cnt * 4 + 2] = beg;
            sched[1 + cnt * 4 + 3] = end;
            cnt++;
        }
        beg = end;
    }
    sched[0] = cnt;
}

// ---------------------------------------------------------------------------
// bf16 split-precision HMMA GEMM, register-staged double-buffered pipeline.
// C = (A (+A2)) @ W + bias; outputs fp32 and/or bf16 hi/lo.
// ---------------------------------------------------------------------------
#define GBM 128
#define GBN 64
#define GKC 32
#define PITCH 40
#define ABUF (GBM * PITCH)          // 5120 elems per hi/lo
#define BBUF (GBN * PITCH)          // 2560
#define BUFSZ (2 * ABUF + 2 * BBUF) // 15360 elems per stage
#define GEMM_SMEM (2 * BUFSZ * 2)   // bytes

__global__ __launch_bounds__(256)
void gemm_mma(const float* __restrict__ A, const float* __restrict__ A2,
              const float* __restrict__ W, const float* __restrict__ bias,
              float* __restrict__ Cf, __nv_bfloat16* __restrict__ Chi,
              __nv_bfloat16* __restrict__ Clo, int M) {
    extern __shared__ __nv_bfloat16 sg[];
    const int tid = threadIdx.x, wid = tid >> 5, lane = tid & 31;
    const int m0 = blockIdx.x * GBM, n0 = blockIdx.y * GBN;
    const int wm = (wid & 3) * 32, wn = (wid >> 2) * 32;

    float acc[2][4][4];
#pragma unroll
    for (int i = 0; i < 2; i++)
#pragma unroll
        for (int j = 0; j < 4; j++)
#pragma unroll
            for (int q = 0; q < 4; q++) acc[i][j][q] = 0.f;

    const int arow = tid >> 3, ag = tid & 7;       // A: row + float4-group
    const int bn = tid & 63, bkb = tid >> 6;       // B: n + k-block

    float4 a4[4], p4[4];
    float bv8[8];
    const bool hasA2 = (A2 != nullptr);

    // fetch chunk into regs
    auto FETCH = [&](int c) {
        const int k0 = c * GKC;
#pragma unroll
        for (int i = 0; i < 4; i++) {
            int row = arow + i * 32, m = m0 + row;
            a4[i] = make_float4(0.f, 0.f, 0.f, 0.f);
            p4[i] = make_float4(0.f, 0.f, 0.f, 0.f);
            if (m < M) {
                a4[i] = *(const float4*)(A + (size_t)m * Dm + k0 + ag * 4);
                if (hasA2) p4[i] = *(const float4*)(A2 + (size_t)m * Dm + k0 + ag * 4);
            }
        }
#pragma unroll
        for (int kk = 0; kk < 8; kk++)
            bv8[kk] = W[(size_t)(k0 + bkb * 8 + kk) * Dm + n0 + bn];
    };
    auto STORE = [&](int buf) {
        __nv_bfloat16* sAh = sg + buf * BUFSZ;
        __nv_bfloat16* sAl = sAh + ABUF;
        __nv_bfloat16* sBh = sAl + ABUF;
        __nv_bfloat16* sBl = sBh + BBUF;
#pragma unroll
        for (int i = 0; i < 4; i++) {
            float x0 = a4[i].x + p4[i].x, x1 = a4[i].y + p4[i].y;
            float x2 = a4[i].z + p4[i].z, x3 = a4[i].w + p4[i].w;
            uint32_t h0, l0, h1, l1;
            split2(x0, x1, h0, l0);
            split2(x2, x3, h1, l1);
            int o = (arow + i * 32) * PITCH + ag * 4;
            *(uint2*)&sAh[o] = make_uint2(h0, h1);
            *(uint2*)&sAl[o] = make_uint2(l0, l1);
        }
        uint32_t hi[4], lo[4];
#pragma unroll
        for (int q = 0; q < 4; q++)
            split2(bv8[q * 2], bv8[q * 2 + 1], hi[q], lo[q]);
        int o = bn * PITCH + bkb * 8;
        *(uint4*)&sBh[o] = make_uint4(hi[0], hi[1], hi[2], hi[3]);
        *(uint4*)&sBl[o] = make_uint4(lo[0], lo[1], lo[2], lo[3]);
    };

    FETCH(0);
    STORE(0);

    const int NC = Dm / GKC;  // 16
    for (int c = 0; c < NC; c++) {
        if (c + 1 < NC) FETCH(c + 1);
        __syncthreads();

        const uint32_t base = smem_u32(sg + (c & 1) * BUFSZ);
        const uint32_t sAhi = base, sAlo = base + ABUF * 2;
        const uint32_t sBhi = base + ABUF * 4, sBlo = base + ABUF * 4 + BBUF * 2;

#pragma unroll
        for (int prod = 0; prod < 3; prod++) {
            const uint32_t sA = (prod == 2) ? sAlo : sAhi;
            const uint32_t sB = (prod == 1) ? sBlo : sBhi;
#pragma unroll
            for (int ks = 0; ks < 2; ks++) {
                uint32_t a[2][4];
#pragma unroll
                for (int im = 0; im < 2; im++) {
                    uint32_t addr = sA + 2 * ((wm + im * 16 + (lane & 15)) * PITCH +
                                              ks * 16 + (lane >> 4) * 8);
                    ldsm_x4(a[im], addr);
                }
                uint32_t b[2][4];
#pragma unroll
                for (int ib = 0; ib < 2; ib++) {
                    int n = wn + ib * 16 + ((lane >> 4) * 8) + (lane & 7);
                    uint32_t addr = sB + 2 * (n * PITCH + ks * 16 + ((lane >> 3) & 1) * 8);
                    ldsm_x4(b[ib], addr);
                }
#pragma unroll
                for (int im = 0; im < 2; im++)
#pragma unroll
                    for (int ib = 0; ib < 2; ib++) {
                        mma_bf16(acc[im][ib * 2 + 0], a[im], b[ib][0], b[ib][1]);
                        mma_bf16(acc[im][ib * 2 + 1], a[im], b[ib][2], b[ib][3]);
                    }
            }
        }
        if (c + 1 < NC) STORE((c + 1) & 1);
    }

    // ---- Epilogue ----
#pragma unroll
    for (int im = 0; im < 2; im++) {
#pragma unroll
        for (int ib = 0; ib < 4; ib++) {
            int col = n0 + wn + ib * 8 + (lane & 3) * 2;
            float2 bb = *(const float2*)(bias + col);
#pragma unroll
            for (int hf = 0; hf < 2; hf++) {
                int r = m0 + wm + im * 16 + (lane >> 2) + hf * 8;
                if (r >= M) continue;
                float ox = acc[im][ib][hf * 2 + 0] + bb.x;
                float oy = acc[im][ib][hf * 2 + 1] + bb.y;
                if (Cf)
                    *(float2*)(Cf + (size_t)r * Dm + col) = make_float2(ox, oy);
                if (Chi) {
                    uint32_t h, l;
                    split2(ox, oy, h, l);
                    *(uint32_t*)(Chi + (size_t)r * Dm + col) = h;
                    *(uint32_t*)(Clo + (size_t)r * Dm + col) = l;
                }
            }
        }
    }
}

// ---------------------------------------------------------------------------
// Flash attention: block = (128-query tile, head). 8 warps x m16 rows;
// each warp owns ALL keys of a 64-key tile -> warp-local online softmax,
// P kept in registers (C-frag == A-frag repack for m16n8k16).
// ---------------------------------------------------------------------------
__global__ __launch_bounds__(256)
void flash_attn(const __nv_bfloat16* __restrict__ Qhi, const __nv_bfloat16* __restrict__ Qlo,
                const __nv_bfloat16* __restrict__ Khi, const __nv_bfloat16* __restrict__ Klo,
                const __nv_bfloat16* __restrict__ Vhi, const __nv_bfloat16* __restrict__ Vlo,
                float* __restrict__ O, const int* __restrict__ sched) {
    __shared__ __nv_bfloat16 smem[4 * KT * KP];   // Khi|Klo|Vhi|Vlo (36.9KB)
    const int cnt = sched[0];
    if (blockIdx.x >= cnt) return;
    const int* e = sched + 1 + blockIdx.x * 4;
    const int q0 = e[0], qlen = e[1], beg = e[2], end = e[3];
    const int h = blockIdx.y;
    const int tid = threadIdx.x, wid = tid >> 5, lane = tid & 31;
    const int wm = wid * 16;

    __nv_bfloat16* sKh = smem;
    __nv_bfloat16* sKl = smem + KT * KP;
    __nv_bfloat16* sVh = smem + 2 * KT * KP;
    __nv_bfloat16* sVl = smem + 3 * KT * KP;
    const uint32_t aKh = smem_u32(sKh), aKl = smem_u32(sKl);
    const uint32_t aVh = smem_u32(sVh), aVl = smem_u32(sVl);

    // ---- Stage Q [128][64] hi/lo into smem (reusing K/V space), grab frags ----
    {
        __nv_bfloat16* sQh = smem;                  // 128*72 elems
        __nv_bfloat16* sQl = smem + QT * KP;
#pragma unroll
        for (int i = 0; i < 4; i++) {
            int idx = tid + i * 256;                // 1024 = 128 rows x 8 groups
            int row = idx >> 3, g = idx & 7;
            uint4 h4 = make_uint4(0, 0, 0, 0), l4 = make_uint4(0, 0, 0, 0);
            if (row < qlen) {
                h4 = *(const uint4*)(Qhi + (size_t)(q0 + row) * Dm + h * HDd + g * 8);
                l4 = *(const uint4*)(Qlo + (size_t)(q0 + row) * Dm + h * HDd + g * 8);
            }
            *(uint4*)&sQh[row * KP + g * 8] = h4;
            *(uint4*)&sQl[row * KP + g * 8] = l4;
        }
        __syncthreads();
    }
    uint32_t qh[4][4], ql[4][4];
    {
        const uint32_t aQh = smem_u32(smem), aQl = smem_u32(smem + QT * KP);
#pragma unroll
        for (int ks = 0; ks < 4; ks++) {
            uint32_t ar = 2 * ((wm + (lane & 15)) * KP + ks * 16 + (lane >> 4) * 8);
            ldsm_x4(qh[ks], aQh + ar);
            ldsm_x4(ql[ks], aQl + ar);
        }
    }
    __syncthreads();

    float oacc[8][4];
#pragma unroll
    for (int t = 0; t < 8; t++)
#pragma unroll
        for (int j = 0; j < 4; j++) oacc[t][j] = 0.f;
    float mrow[2] = {-1e30f, -1e30f}, lrow[2] = {0.f, 0.f};

    const int nk = (end - beg + KT - 1) / KT;
    for (int kt = 0; kt < nk; kt++) {
        const int j0 = beg + kt * KT;
        // ---- load K & V tiles ----
#pragma unroll
        for (int i = 0; i < 2; i++) {
            int idx = tid + i * 256;                // 512 = 64 rows x 8 groups
            int row = idx >> 3, g = idx & 7;
            int key = j0 + row;
            uint4 kh = make_uint4(0, 0, 0, 0), kl = kh, vh = kh, vl = kh;
            if (key < end) {
                size_t off = (size_t)key * Dm + h * HDd + g * 8;
                kh = *(const uint4*)(Khi + off);
                kl = *(const uint4*)(Klo + off);
                vh = *(const uint4*)(Vhi + off);
                vl = *(const uint4*)(Vlo + off);
            }
            int o = row * KP + g * 8;
            *(uint4*)&sKh[o] = kh;
            *(uint4*)&sKl[o] = kl;
            *(uint4*)&sVh[o] = vh;
            *(uint4*)&sVl[o] = vl;
        }
        __syncthreads();

        // ---- S = Q K^T (split precision), warp covers all 64 keys ----
        float c[8][4];
#pragma unroll
        for (int t = 0; t < 8; t++)
#pragma unroll
            for (int j = 0; j < 4; j++) c[t][j] = 0.f;
#pragma unroll
        for (int ks = 0; ks < 4; ks++) {
#pragma unroll
            for (int nb = 0; nb < 4; nb++) {
                uint32_t br = 2 * ((nb * 16 + (lane >> 4) * 8 + (lane & 7)) * KP +
                                   ks * 16 + ((lane >> 3) & 1) * 8);
                uint32_t bh[4], bl[4];
                ldsm_x4(bh, aKh + br);
                ldsm_x4(bl, aKl + br);
                mma_bf16(c[2 * nb], qh[ks], bh[0], bh[1]);
                mma_bf16(c[2 * nb], qh[ks], bl[0], bl[1]);
                mma_bf16(c[2 * nb], ql[ks], bh[0], bh[1]);
                mma_bf16(c[2 * nb + 1], qh[ks], bh[2], bh[3]);
                mma_bf16(c[2 * nb + 1], qh[ks], bl[2], bl[3]);
                mma_bf16(c[2 * nb + 1], ql[ks], bh[2], bh[3]);
            }
        }

        // ---- mask + scale ----
#pragma unroll
        for (int t = 0; t < 8; t++) {
            int k0 = j0 + t * 8 + (lane & 3) * 2;
            bool v0 = k0 < end, v1 = k0 + 1 < end;
            c[t][0] = v0 ? c[t][0] * 0.125f : -1e30f;
            c[t][1] = v1 ? c[t][1] * 0.125f : -1e30f;
            c[t][2] = v0 ? c[t][2] * 0.125f : -1e30f;
            c[t][3] = v1 ? c[t][3] * 0.125f : -1e30f;
        }

        // ---- online softmax (quad-local: rows lane>>2, +8) ----
#pragma unroll
        for (int rh = 0; rh < 2; rh++) {
            const int i0 = rh * 2;
            float mx = -1e30f;
#pragma unroll
            for (int t = 0; t < 8; t++)
                mx = fmaxf(mx, fmaxf(c[t][i0], c[t][i0 + 1]));
            mx = fmaxf(mx, __shfl_xor_sync(0xffffffffu, mx, 1));
            mx = fmaxf(mx, __shfl_xor_sync(0xffffffffu, mx, 2));
            float mnew = fmaxf(mrow[rh], mx);
            float alpha = __expf(mrow[rh] - mnew);
            float ps = 0.f;
#pragma unroll
            for (int t = 0; t < 8; t++) {
                float p0 = __expf(c[t][i0] - mnew);
                float p1 = __expf(c[t][i0 + 1] - mnew);
                c[t][i0] = p0;
                c[t][i0 + 1] = p1;
                ps += p0 + p1;
            }
            ps += __shfl_xor_sync(0xffffffffu, ps, 1);
            ps += __shfl_xor_sync(0xffffffffu, ps, 2);
            lrow[rh] = lrow[rh] * alpha + ps;
            mrow[rh] = mnew;
#pragma unroll
            for (int t = 0; t < 8; t++) {
                oacc[t][i0] *= alpha;
                oacc[t][i0 + 1] *= alpha;
            }
        }

        // ---- P (C-frags) -> A-frags, bf16 hi/lo, in registers ----
        uint32_t ph[4][4], pl[4][4];
#pragma unroll
        for (int s = 0; s < 4; s++) {
            int t0 = 2 * s, t1 = 2 * s + 1;
            split2(c[t0][0], c[t0][1], ph[s][0], pl[s][0]);
            split2(c[t0][2], c[t0][3], ph[s][1], pl[s][1]);
            split2(c[t1][0], c[t1][1], ph[s][2], pl[s][2]);
            split2(c[t1][2], c[t1][3], ph[s][3], pl[s][3]);
        }

        // ---- O += P V ----
#pragma unroll
        for (int s = 0; s < 4; s++) {
            int mat = lane >> 3, rin = lane & 7;
            int keyr = s * 16 + (mat & 1) * 8 + rin;
#pragma unroll
            for (int d = 0; d < 4; d++) {
                uint32_t ad = 2 * (keyr * KP + d * 16 + (mat >> 1) * 8);
                uint32_t vh[4], vl[4];
                ldsm_x4_t(vh, aVh + ad);
                ldsm_x4_t(vl, aVl + ad);
                mma_bf16(oacc[2 * d], ph[s], vh[0], vh[1]);
                mma_bf16(oacc[2 * d], ph[s], vl[0], vl[1]);
                mma_bf16(oacc[2 * d], pl[s], vh[0], vh[1]);
                mma_bf16(oacc[2 * d + 1], ph[s], vh[2], vh[3]);
                mma_bf16(oacc[2 * d + 1], ph[s], vl[2], vl[3]);
                mma_bf16(oacc[2 * d + 1], pl[s], vh[2], vh[3]);
            }
        }
        __syncthreads();
    }

    // ---- normalize + write ----
#pragma unroll
    for (int rh = 0; rh < 2; rh++) {
        float inv = 1.f / lrow[rh];
        int row = wm + (lane >> 2) + rh * 8;
        if (row >= qlen) continue;
#pragma unroll
        for (int t = 0; t < 8; t++) {
            int col = h * HDd + t * 8 + (lane & 3) * 2;
            *(float2*)(O + (size_t)(q0 + row) * Dm + col) =
                make_float2(oacc[t][rh * 2] * inv, oacc[t][rh * 2 + 1] * inv);
        }
    }
}

// ---------------------------------------------------------------------------
extern "C" void kernel_launch(void* const* d_in, const int* in_sizes, int n_in,
                              void* d_out, int out_size) {
    const float* xq  = (const float*)d_in[0];
    const float* xk  = (const float*)d_in[1];
    const float* pos = (const float*)d_in[2];
    const int*   ch  = (const int*)d_in[3];
    const float* Wq = (const float*)d_in[4];  const float* bq = (const float*)d_in[5];
    const float* Wk = (const float*)d_in[6];  const float* bk = (const float*)d_in[7];
    const float* Wv = (const float*)d_in[8];  const float* bv = (const float*)d_in[9];
    const float* Wo = (const float*)d_in[10]; const float* bo = (const float*)d_in[11];
    float* out = (float*)d_out;

    const int T = in_sizes[0] / Dm;       // 3136
    const int n_ch = in_sizes[3];         // 4

    void* p = nullptr;
    cudaGetSymbolAddress(&p, g_scratch);
    float* scr = (float*)p;
    const size_t SZ = (size_t)MAXT * Dm;
    float* Ob = scr;
    __nv_bfloat16* b16 = (__nv_bfloat16*)(scr + SZ);
    __nv_bfloat16* Qhi = b16 + 0 * SZ;
    __nv_bfloat16* Qlo = b16 + 1 * SZ;
    __nv_bfloat16* Khi = b16 + 2 * SZ;
    __nv_bfloat16* Klo = b16 + 3 * SZ;
    __nv_bfloat16* Vhi = b16 + 4 * SZ;
    __nv_bfloat16* Vlo = b16 + 5 * SZ;

    void* ps = nullptr;
    cudaGetSymbolAddress(&ps, g_sched);
    int* sched = (int*)ps;

    cudaFuncSetAttribute(gemm_mma, cudaFuncAttributeMaxDynamicSharedMemorySize, GEMM_SMEM);

    setup_sched<<<1, 32>>>(ch, n_ch, sched);

    dim3 gg((T + GBM - 1) / GBM, Dm / GBN);
    gemm_mma<<<gg, 256, GEMM_SMEM>>>(xq, pos,     Wq, bq, nullptr, Qhi, Qlo, T);
    gemm_mma<<<gg, 256, GEMM_SMEM>>>(xk, pos,     Wk, bk, nullptr, Khi, Klo, T);
    gemm_mma<<<gg, 256, GEMM_SMEM>>>(xk, nullptr, Wv, bv, nullptr, Vhi, Vlo, T);

    dim3 ga(T / QT + n_ch, Hn);
    flash_attn<<<ga, 256>>>(Qhi, Qlo, Khi, Klo, Vhi, Vlo, Ob, sched);

    gemm_mma<<<gg, 256, GEMM_SMEM>>>(Ob, nullptr, Wo, bo, out, nullptr, nullptr, T);
}

// round 7
// speedup vs baseline: 3.8736x; 1.9654x over previous
#include <cuda_runtime.h>
#include <cuda_bf16.h>
#include <cstdint>

#define Dm   512
#define Hn   8
#define HDd  64
#define Sg   196
#define MAXT 3200    // 25 * 128 >= T=3136
#define QT   128     // queries per flash block
#define KT   64      // keys per flash tile
#define KP   72      // attention smem pitch (bf16)

// bf16 scratch: 14 token-arrays [MAXT][Dm] + 8 weight arrays [Dm][Dm] (~50MB)
__device__ __nv_bfloat16 g_bf[14 * MAXT * Dm + 8 * Dm * Dm];
__device__ int g_sched[256];

__device__ __forceinline__ uint32_t smem_u32(const void* p) {
    uint32_t a;
    asm("{ .reg .u64 t; cvta.to.shared.u64 t, %1; cvt.u32.u64 %0, t; }" : "=r"(a) : "l"(p));
    return a;
}
__device__ __forceinline__ void ldsm_x4(uint32_t* r, uint32_t addr) {
    asm volatile("ldmatrix.sync.aligned.m8n8.x4.shared.b16 {%0,%1,%2,%3}, [%4];"
                 : "=r"(r[0]), "=r"(r[1]), "=r"(r[2]), "=r"(r[3]) : "r"(addr));
}
__device__ __forceinline__ void ldsm_x4_t(uint32_t* r, uint32_t addr) {
    asm volatile("ldmatrix.sync.aligned.m8n8.x4.trans.shared.b16 {%0,%1,%2,%3}, [%4];"
                 : "=r"(r[0]), "=r"(r[1]), "=r"(r[2]), "=r"(r[3]) : "r"(addr));
}
__device__ __forceinline__ void mma_bf16(float* c, const uint32_t* a, uint32_t b0, uint32_t b1) {
    asm volatile("mma.sync.aligned.m16n8k16.row.col.f32.bf16.bf16.f32 "
                 "{%0,%1,%2,%3}, {%4,%5,%6,%7}, {%8,%9}, {%0,%1,%2,%3};"
                 : "+f"(c[0]), "+f"(c[1]), "+f"(c[2]), "+f"(c[3])
                 : "r"(a[0]), "r"(a[1]), "r"(a[2]), "r"(a[3]), "r"(b0), "r"(b1));
}
__device__ __forceinline__ uint32_t pack2(__nv_bfloat16 x, __nv_bfloat16 y) {
    __nv_bfloat162 t(x, y);
    return *(uint32_t*)&t;
}
__device__ __forceinline__ void split2(float x, float y, uint32_t& hi, uint32_t& lo) {
    __nv_bfloat16 hx = __float2bfloat16(x), hy = __float2bfloat16(y);
    __nv_bfloat16 lx = __float2bfloat16(x - __bfloat162float(hx));
    __nv_bfloat16 ly = __float2bfloat16(y - __bfloat162float(hy));
    hi = pack2(hx, hy);
    lo = pack2(lx, ly);
}

// ---------------------------------------------------------------------------
// Schedule: per-segment q-tiles of QT. Entry: {q0, qlen, beg, end}.
// ---------------------------------------------------------------------------
__global__ void setup_sched(const int* __restrict__ channels, int n_ch,
                            int* __restrict__ sched) {
    if (threadIdx.x != 0 || blockIdx.x != 0) return;
    int cnt = 0, beg = 0;
    for (int i = 0; i < n_ch; i++) {
        int len = channels[i] * Sg, end = beg + len;
        for (int j = 0; j < len; j += QT) {
            sched[1 + cnt * 4 + 0] = beg + j;
            sched[1 + cnt * 4 + 1] = (len - j < QT) ? (len - j) : QT;
            sched[1 + cnt * 4 + 2] = beg;
            sched[1 + cnt * 4 + 3] = end;
            cnt++;
        }
        beg = end;
    }
    sched[0] = cnt;
}

// ---------------------------------------------------------------------------
// Input convert: (xq+pos), (xk+pos), xk -> bf16 hi/lo, [T][Dm].
// ---------------------------------------------------------------------------
__global__ void conv_in(const float* __restrict__ xq, const float* __restrict__ xk,
                        const float* __restrict__ pos,
                        __nv_bfloat16* XQh, __nv_bfloat16* XQl,
                        __nv_bfloat16* XPh, __nv_bfloat16* XPl,
                        __nv_bfloat16* XKh, __nv_bfloat16* XKl, int n4) {
    int i = blockIdx.x * blockDim.x + threadIdx.x;
    if (i >= n4) return;
    float4 q = ((const float4*)xq)[i];
    float4 k = ((const float4*)xk)[i];
    float4 p = ((const float4*)pos)[i];
    uint32_t h0, l0, h1, l1;
    split2(q.x + p.x, q.y + p.y, h0, l0);
    split2(q.z + p.z, q.w + p.w, h1, l1);
    *(uint2*)&XQh[i * 4] = make_uint2(h0, h1);
    *(uint2*)&XQl[i * 4] = make_uint2(l0, l1);
    split2(k.x + p.x, k.y + p.y, h0, l0);
    split2(k.z + p.z, k.w + p.w, h1, l1);
    *(uint2*)&XPh[i * 4] = make_uint2(h0, h1);
    *(uint2*)&XPl[i * 4] = make_uint2(l0, l1);
    split2(k.x, k.y, h0, l0);
    split2(k.z, k.w, h1, l1);
    *(uint2*)&XKh[i * 4] = make_uint2(h0, h1);
    *(uint2*)&XKl[i * 4] = make_uint2(l0, l1);
}

// ---------------------------------------------------------------------------
// Weight transpose-convert: W[k][n] fp32 -> Wt[n][k] bf16 hi/lo.
// ---------------------------------------------------------------------------
struct WcArgs {
    const float* W[4];
    __nv_bfloat16* Wh[4];
    __nv_bfloat16* Wl[4];
};
__global__ void conv_w(WcArgs wa) {
    __shared__ float t[32][33];
    const float* W = wa.W[blockIdx.z];
    __nv_bfloat16* Wh = wa.Wh[blockIdx.z];
    __nv_bfloat16* Wl = wa.Wl[blockIdx.z];
    int n0 = blockIdx.x * 32, k0 = blockIdx.y * 32;
    int tx = threadIdx.x, ty = threadIdx.y;
#pragma unroll
    for (int i = 0; i < 4; i++)
        t[ty + i * 8][tx] = W[(size_t)(k0 + ty + i * 8) * Dm + n0 + tx];
    __syncthreads();
#pragma unroll
    for (int i = 0; i < 4; i++) {
        int n = n0 + ty + i * 8;
        float v = t[tx][ty + i * 8];
        __nv_bfloat16 h = __float2bfloat16(v);
        __nv_bfloat16 l = __float2bfloat16(v - __bfloat162float(h));
        Wh[(size_t)n * Dm + k0 + tx] = h;
        Wl[(size_t)n * Dm + k0 + tx] = l;
    }
}

// ---------------------------------------------------------------------------
// Pure-bf16 split-precision GEMM, cp.async double-buffered.
// C = A @ W^T(+bias); A=[M][K] hi/lo, W=[N][K] hi/lo (pre-transposed).
// Tile 128x64, k-chunk 64, 256 thr, warp 32x32. XOR-swizzled 128B smem rows.
// ---------------------------------------------------------------------------
struct GemmArgs {
    const __nv_bfloat16 *Ah[3], *Al[3], *Wh[3], *Wl[3];
    const float* bias[3];
    __nv_bfloat16 *Ch[3], *Cl[3];
    float* Cf[3];
};
#define STG 49152              // stage bytes: Ahi 16K | Alo 16K | Bhi 8K | Blo 8K
#define GEMM_SMEM (2 * STG)

__global__ __launch_bounds__(256, 2)
void gemm_bf16(GemmArgs ga, int M) {
    extern __shared__ char sg[];
    const int z = blockIdx.z;
    const __nv_bfloat16* Ah = ga.Ah[z];
    const __nv_bfloat16* Al = ga.Al[z];
    const __nv_bfloat16* Wh = ga.Wh[z];
    const __nv_bfloat16* Wl = ga.Wl[z];
    const int tid = threadIdx.x, wid = tid >> 5, lane = tid & 31;
    const int m0 = blockIdx.x * 128, n0 = blockIdx.y * 64;
    const int wm = (wid & 3) * 32, wn = (wid >> 2) * 32;
    const uint32_t sb = smem_u32(sg);

    float acc[2][4][4];
#pragma unroll
    for (int i = 0; i < 2; i++)
#pragma unroll
        for (int j = 0; j < 4; j++)
#pragma unroll
            for (int q = 0; q < 4; q++) acc[i][j][q] = 0.f;

    auto ISSUE = [&](int c, int buf) {
        const uint32_t base = sb + buf * STG;
        const int ko = c * 64;
#pragma unroll
        for (int i = 0; i < 8; i++) {          // A: 2048 granules / 256 thr
            int idx = tid + i * 256;
            int arr = idx >> 10, rem = idx & 1023;
            int row = rem >> 3, g = rem & 7;
            uint32_t dst = base + arr * 16384 + row * 128 + ((g ^ (row & 7)) * 16);
            const __nv_bfloat16* src = (arr ? Al : Ah) + (size_t)(m0 + row) * Dm + ko + g * 8;
            int sz = (m0 + row) < M ? 16 : 0;
            asm volatile("cp.async.cg.shared.global [%0], [%1], 16, %2;"
                         :: "r"(dst), "l"(src), "r"(sz));
        }
#pragma unroll
        for (int i = 0; i < 4; i++) {          // B: 1024 granules / 256 thr
            int idx = tid + i * 256;
            int arr = idx >> 9, rem = idx & 511;
            int row = rem >> 3, g = rem & 7;
            uint32_t dst = base + 32768 + arr * 8192 + row * 128 + ((g ^ (row & 7)) * 16);
            const __nv_bfloat16* src = (arr ? Wl : Wh) + (size_t)(n0 + row) * Dm + ko + g * 8;
            asm volatile("cp.async.cg.shared.global [%0], [%1], 16;"
                         :: "r"(dst), "l"(src));
        }
        asm volatile("cp.async.commit_group;");
    };

    ISSUE(0, 0);
    const int NC = Dm / 64;   // 8
    for (int c = 0; c < NC; c++) {
        if (c + 1 < NC) {
            ISSUE(c + 1, (c + 1) & 1);
            asm volatile("cp.async.wait_group 1;");
        } else {
            asm volatile("cp.async.wait_group 0;");
        }
        __syncthreads();

        const uint32_t base = sb + (c & 1) * STG;
        const uint32_t sAh = base, sAl = base + 16384;
        const uint32_t sBh = base + 32768, sBl = base + 40960;

#pragma unroll
        for (int ks = 0; ks < 4; ks++) {
            uint32_t ah[2][4], al[2][4], bh[2][4], bl[2][4];
#pragma unroll
            for (int im = 0; im < 2; im++) {
                int row = wm + im * 16 + (lane & 15);
                int g = ks * 2 + (lane >> 4);
                uint32_t off = row * 128 + ((g ^ (row & 7)) * 16);
                ldsm_x4(ah[im], sAh + off);
                ldsm_x4(al[im], sAl + off);
            }
#pragma unroll
            for (int ib = 0; ib < 2; ib++) {
                int rn = wn + ib * 16 + (lane >> 4) * 8 + (lane & 7);
                int g = ks * 2 + ((lane >> 3) & 1);
                uint32_t off = rn * 128 + ((g ^ (rn & 7)) * 16);
                ldsm_x4(bh[ib], sBh + off);
                ldsm_x4(bl[ib], sBl + off);
            }
#pragma unroll
            for (int im = 0; im < 2; im++)
#pragma unroll
                for (int ib = 0; ib < 2; ib++) {
                    mma_bf16(acc[im][ib * 2 + 0], ah[im], bh[ib][0], bh[ib][1]);
                    mma_bf16(acc[im][ib * 2 + 1], ah[im], bh[ib][2], bh[ib][3]);
                    mma_bf16(acc[im][ib * 2 + 0], ah[im], bl[ib][0], bl[ib][1]);
                    mma_bf16(acc[im][ib * 2 + 1], ah[im], bl[ib][2], bl[ib][3]);
                    mma_bf16(acc[im][ib * 2 + 0], al[im], bh[ib][0], bh[ib][1]);
                    mma_bf16(acc[im][ib * 2 + 1], al[im], bh[ib][2], bh[ib][3]);
                }
        }
        __syncthreads();
    }

    // ---- Epilogue ----
    const float* bias = ga.bias[z];
    __nv_bfloat16* Ch = ga.Ch[z];
    __nv_bfloat16* Cl = ga.Cl[z];
    float* Cf = ga.Cf[z];
#pragma unroll
    for (int im = 0; im < 2; im++) {
#pragma unroll
        for (int ib = 0; ib < 4; ib++) {
            int col = n0 + wn + ib * 8 + (lane & 3) * 2;
            float2 bb = *(const float2*)(bias + col);
#pragma unroll
            for (int hf = 0; hf < 2; hf++) {
                int r = m0 + wm + im * 16 + (lane >> 2) + hf * 8;
                if (r >= M) continue;
                float ox = acc[im][ib][hf * 2 + 0] + bb.x;
                float oy = acc[im][ib][hf * 2 + 1] + bb.y;
                if (Cf)
                    *(float2*)(Cf + (size_t)r * Dm + col) = make_float2(ox, oy);
                if (Ch) {
                    uint32_t h, l;
                    split2(ox, oy, h, l);
                    *(uint32_t*)(Ch + (size_t)r * Dm + col) = h;
                    *(uint32_t*)(Cl + (size_t)r * Dm + col) = l;
                }
            }
        }
    }
}

// ---------------------------------------------------------------------------
// Flash attention (validated round 6), O written as bf16 hi/lo.
// ---------------------------------------------------------------------------
__global__ __launch_bounds__(256)
void flash_attn(const __nv_bfloat16* __restrict__ Qhi, const __nv_bfloat16* __restrict__ Qlo,
                const __nv_bfloat16* __restrict__ Khi, const __nv_bfloat16* __restrict__ Klo,
                const __nv_bfloat16* __restrict__ Vhi, const __nv_bfloat16* __restrict__ Vlo,
                __nv_bfloat16* __restrict__ Oh, __nv_bfloat16* __restrict__ Ol,
                const int* __restrict__ sched) {
    __shared__ __nv_bfloat16 smem[4 * KT * KP];
    const int cnt = sched[0];
    if (blockIdx.x >= cnt) return;
    const int* e = sched + 1 + blockIdx.x * 4;
    const int q0 = e[0], qlen = e[1], beg = e[2], end = e[3];
    const int h = blockIdx.y;
    const int tid = threadIdx.x, wid = tid >> 5, lane = tid & 31;
    const int wm = wid * 16;

    __nv_bfloat16* sKh = smem;
    __nv_bfloat16* sKl = smem + KT * KP;
    __nv_bfloat16* sVh = smem + 2 * KT * KP;
    __nv_bfloat16* sVl = smem + 3 * KT * KP;
    const uint32_t aKh = smem_u32(sKh), aKl = smem_u32(sKl);
    const uint32_t aVh = smem_u32(sVh), aVl = smem_u32(sVl);

    {
        __nv_bfloat16* sQh = smem;
        __nv_bfloat16* sQl = smem + QT * KP;
#pragma unroll
        for (int i = 0; i < 4; i++) {
            int idx = tid + i * 256;
            int row = idx >> 3, g = idx & 7;
            uint4 h4 = make_uint4(0, 0, 0, 0), l4 = make_uint4(0, 0, 0, 0);
            if (row < qlen) {
                h4 = *(const uint4*)(Qhi + (size_t)(q0 + row) * Dm + h * HDd + g * 8);
                l4 = *(const uint4*)(Qlo + (size_t)(q0 + row) * Dm + h * HDd + g * 8);
            }
            *(uint4*)&sQh[row * KP + g * 8] = h4;
            *(uint4*)&sQl[row * KP + g * 8] = l4;
        }
        __syncthreads();
    }
    uint32_t qh[4][4], ql[4][4];
    {
        const uint32_t aQh = smem_u32(smem), aQl = smem_u32(smem + QT * KP);
#pragma unroll
        for (int ks = 0; ks < 4; ks++) {
            uint32_t ar = 2 * ((wm + (lane & 15)) * KP + ks * 16 + (lane >> 4) * 8);
            ldsm_x4(qh[ks], aQh + ar);
            ldsm_x4(ql[ks], aQl + ar);
        }
    }
    __syncthreads();

    float oacc[8][4];
#pragma unroll
    for (int t = 0; t < 8; t++)
#pragma unroll
        for (int j = 0; j < 4; j++) oacc[t][j] = 0.f;
    float mrow[2] = {-1e30f, -1e30f}, lrow[2] = {0.f, 0.f};

    const int nk = (end - beg + KT - 1) / KT;
    for (int kt = 0; kt < nk; kt++) {
        const int j0 = beg + kt * KT;
#pragma unroll
        for (int i = 0; i < 2; i++) {
            int idx = tid + i * 256;
            int row = idx >> 3, g = idx & 7;
            int key = j0 + row;
            uint4 kh = make_uint4(0, 0, 0, 0), kl = kh, vh = kh, vl = kh;
            if (key < end) {
                size_t off = (size_t)key * Dm + h * HDd + g * 8;
                kh = *(const uint4*)(Khi + off);
                kl = *(const uint4*)(Klo + off);
                vh = *(const uint4*)(Vhi + off);
                vl = *(const uint4*)(Vlo + off);
            }
            int o = row * KP + g * 8;
            *(uint4*)&sKh[o] = kh;
            *(uint4*)&sKl[o] = kl;
            *(uint4*)&sVh[o] = vh;
            *(uint4*)&sVl[o] = vl;
        }
        __syncthreads();

        float c[8][4];
#pragma unroll
        for (int t = 0; t < 8; t++)
#pragma unroll
            for (int j = 0; j < 4; j++) c[t][j] = 0.f;
#pragma unroll
        for (int ks = 0; ks < 4; ks++) {
#pragma unroll
            for (int nb = 0; nb < 4; nb++) {
                uint32_t br = 2 * ((nb * 16 + (lane >> 4) * 8 + (lane & 7)) * KP +
                                   ks * 16 + ((lane >> 3) & 1) * 8);
                uint32_t bh[4], bl[4];
                ldsm_x4(bh, aKh + br);
                ldsm_x4(bl, aKl + br);
                mma_bf16(c[2 * nb], qh[ks], bh[0], bh[1]);
                mma_bf16(c[2 * nb], qh[ks], bl[0], bl[1]);
                mma_bf16(c[2 * nb], ql[ks], bh[0], bh[1]);
                mma_bf16(c[2 * nb + 1], qh[ks], bh[2], bh[3]);
                mma_bf16(c[2 * nb + 1], qh[ks], bl[2], bl[3]);
                mma_bf16(c[2 * nb + 1], ql[ks], bh[2], bh[3]);
            }
        }

#pragma unroll
        for (int t = 0; t < 8; t++) {
            int k0 = j0 + t * 8 + (lane & 3) * 2;
            bool v0 = k0 < end, v1 = k0 + 1 < end;
            c[t][0] = v0 ? c[t][0] * 0.125f : -1e30f;
            c[t][1] = v1 ? c[t][1] * 0.125f : -1e30f;
            c[t][2] = v0 ? c[t][2] * 0.125f : -1e30f;
            c[t][3] = v1 ? c[t][3] * 0.125f : -1e30f;
        }

#pragma unroll
        for (int rh = 0; rh < 2; rh++) {
            const int i0 = rh * 2;
            float mx = -1e30f;
#pragma unroll
            for (int t = 0; t < 8; t++)
                mx = fmaxf(mx, fmaxf(c[t][i0], c[t][i0 + 1]));
            mx = fmaxf(mx, __shfl_xor_sync(0xffffffffu, mx, 1));
            mx = fmaxf(mx, __shfl_xor_sync(0xffffffffu, mx, 2));
            float mnew = fmaxf(mrow[rh], mx);
            float alpha = __expf(mrow[rh] - mnew);
            float ps = 0.f;
#pragma unroll
            for (int t = 0; t < 8; t++) {
                float p0 = __expf(c[t][i0] - mnew);
                float p1 = __expf(c[t][i0 + 1] - mnew);
                c[t][i0] = p0;
                c[t][i0 + 1] = p1;
                ps += p0 + p1;
            }
            ps += __shfl_xor_sync(0xffffffffu, ps, 1);
            ps += __shfl_xor_sync(0xffffffffu, ps, 2);
            lrow[rh] = lrow[rh] * alpha + ps;
            mrow[rh] = mnew;
#pragma unroll
            for (int t = 0; t < 8; t++) {
                oacc[t][i0] *= alpha;
                oacc[t][i0 + 1] *= alpha;
            }
        }

        uint32_t ph[4][4], pl[4][4];
#pragma unroll
        for (int s = 0; s < 4; s++) {
            int t0 = 2 * s, t1 = 2 * s + 1;
            split2(c[t0][0], c[t0][1], ph[s][0], pl[s][0]);
            split2(c[t0][2], c[t0][3], ph[s][1], pl[s][1]);
            split2(c[t1][0], c[t1][1], ph[s][2], pl[s][2]);
            split2(c[t1][2], c[t1][3], ph[s][3], pl[s][3]);
        }

#pragma unroll
        for (int s = 0; s < 4; s++) {
            int mat = lane >> 3, rin = lane & 7;
            int keyr = s * 16 + (mat & 1) * 8 + rin;
#pragma unroll
            for (int d = 0; d < 4; d++) {
                uint32_t ad = 2 * (keyr * KP + d * 16 + (mat >> 1) * 8);
                uint32_t vh[4], vl[4];
                ldsm_x4_t(vh, aVh + ad);
                ldsm_x4_t(vl, aVl + ad);
                mma_bf16(oacc[2 * d], ph[s], vh[0], vh[1]);
                mma_bf16(oacc[2 * d], ph[s], vl[0], vl[1]);
                mma_bf16(oacc[2 * d], pl[s], vh[0], vh[1]);
                mma_bf16(oacc[2 * d + 1], ph[s], vh[2], vh[3]);
                mma_bf16(oacc[2 * d + 1], ph[s], vl[2], vl[3]);
                mma_bf16(oacc[2 * d + 1], pl[s], vh[2], vh[3]);
            }
        }
        __syncthreads();
    }

#pragma unroll
    for (int rh = 0; rh < 2; rh++) {
        float inv = 1.f / lrow[rh];
        int row = wm + (lane >> 2) + rh * 8;
        if (row >= qlen) continue;
#pragma unroll
        for (int t = 0; t < 8; t++) {
            int col = h * HDd + t * 8 + (lane & 3) * 2;
            uint32_t hh, ll;
            split2(oacc[t][rh * 2] * inv, oacc[t][rh * 2 + 1] * inv, hh, ll);
            *(uint32_t*)(Oh + (size_t)(q0 + row) * Dm + col) = hh;
            *(uint32_t*)(Ol + (size_t)(q0 + row) * Dm + col) = ll;
        }
    }
}

// ---------------------------------------------------------------------------
extern "C" void kernel_launch(void* const* d_in, const int* in_sizes, int n_in,
                              void* d_out, int out_size) {
    const float* xq  = (const float*)d_in[0];
    const float* xk  = (const float*)d_in[1];
    const float* pos = (const float*)d_in[2];
    const int*   ch  = (const int*)d_in[3];
    const float* Wq = (const float*)d_in[4];  const float* bq = (const float*)d_in[5];
    const float* Wk = (const float*)d_in[6];  const float* bk = (const float*)d_in[7];
    const float* Wv = (const float*)d_in[8];  const float* bv = (const float*)d_in[9];
    const float* Wo = (const float*)d_in[10]; const float* bo = (const float*)d_in[11];
    float* out = (float*)d_out;

    const int T = in_sizes[0] / Dm;       // 3136
    const int n_ch = in_sizes[3];         // 4

    void* p = nullptr;
    cudaGetSymbolAddress(&p, g_bf);
    __nv_bfloat16* b = (__nv_bfloat16*)p;
    const size_t SZ = (size_t)MAXT * Dm;
    const size_t WZ = (size_t)Dm * Dm;
    __nv_bfloat16 *XQh = b + 0*SZ,  *XQl = b + 1*SZ;
    __nv_bfloat16 *XPh = b + 2*SZ,  *XPl = b + 3*SZ;
    __nv_bfloat16 *XKh = b + 4*SZ,  *XKl = b + 5*SZ;
    __nv_bfloat16 *Qh  = b + 6*SZ,  *Ql  = b + 7*SZ;
    __nv_bfloat16 *Kh  = b + 8*SZ,  *Kl  = b + 9*SZ;
    __nv_bfloat16 *Vh  = b + 10*SZ, *Vl  = b + 11*SZ;
    __nv_bfloat16 *Oh  = b + 12*SZ, *Ol  = b + 13*SZ;
    __nv_bfloat16* w = b + 14*SZ;
    __nv_bfloat16 *Wqh = w + 0*WZ, *Wql = w + 1*WZ;
    __nv_bfloat16 *Wkh = w + 2*WZ, *Wkl = w + 3*WZ;
    __nv_bfloat16 *Wvh = w + 4*WZ, *Wvl = w + 5*WZ;
    __nv_bfloat16 *Woh = w + 6*WZ, *Wol = w + 7*WZ;

    void* ps = nullptr;
    cudaGetSymbolAddress(&ps, g_sched);
    int* sched = (int*)ps;

    cudaFuncSetAttribute(gemm_bf16, cudaFuncAttributeMaxDynamicSharedMemorySize, GEMM_SMEM);

    setup_sched<<<1, 32>>>(ch, n_ch, sched);

    int n4 = T * Dm / 4;
    conv_in<<<(n4 + 255) / 256, 256>>>(xq, xk, pos, XQh, XQl, XPh, XPl, XKh, XKl, n4);

    WcArgs wa;
    wa.W[0] = Wq; wa.Wh[0] = Wqh; wa.Wl[0] = Wql;
    wa.W[1] = Wk; wa.Wh[1] = Wkh; wa.Wl[1] = Wkl;
    wa.W[2] = Wv; wa.Wh[2] = Wvh; wa.Wl[2] = Wvl;
    wa.W[3] = Wo; wa.Wh[3] = Woh; wa.Wl[3] = Wol;
    conv_w<<<dim3(16, 16, 4), dim3(32, 8)>>>(wa);

    // QKV fused: z=0 Q, z=1 K, z=2 V
    GemmArgs g1;
    g1.Ah[0] = XQh; g1.Al[0] = XQl; g1.Wh[0] = Wqh; g1.Wl[0] = Wql;
    g1.bias[0] = bq; g1.Ch[0] = Qh; g1.Cl[0] = Ql; g1.Cf[0] = nullptr;
    g1.Ah[1] = XPh; g1.Al[1] = XPl; g1.Wh[1] = Wkh; g1.Wl[1] = Wkl;
    g1.bias[1] = bk; g1.Ch[1] = Kh; g1.Cl[1] = Kl; g1.Cf[1] = nullptr;
    g1.Ah[2] = XKh; g1.Al[2] = XKl; g1.Wh[2] = Wvh; g1.Wl[2] = Wvl;
    g1.bias[2] = bv; g1.Ch[2] = Vh; g1.Cl[2] = Vl; g1.Cf[2] = nullptr;
    gemm_bf16<<<dim3(MAXT / 128, Dm / 64, 3), 256, GEMM_SMEM>>>(g1, T);

    dim3 ga(T / QT + n_ch, Hn);
    flash_attn<<<ga, 256>>>(Qh, Ql, Kh, Kl, Vh, Vl, Oh, Ol, sched);

    GemmArgs g2;
    g2.Ah[0] = Oh; g2.Al[0] = Ol; g2.Wh[0] = Woh; g2.Wl[0] = Wol;
    g2.bias[0] = bo; g2.Ch[0] = nullptr; g2.Cl[0] = nullptr; g2.Cf[0] = out;
    for (int i = 1; i < 3; i++) {
        g2.Ah[i] = Oh; g2.Al[i] = Ol; g2.Wh[i] = Woh; g2.Wl[i] = Wol;
        g2.bias[i] = bo; g2.Ch[i] = nullptr; g2.Cl[i] = nullptr; g2.Cf[i] = nullptr;
    }
    gemm_bf16<<<dim3(MAXT / 128, Dm / 64, 1), 256, GEMM_SMEM>>>(g2, T);
}

// round 8
// speedup vs baseline: 4.0015x; 1.0330x over previous
#include <cuda_runtime.h>
#include <cuda_bf16.h>
#include <cstdint>

#define Dm   512
#define Hn   8
#define HDd  64
#define Sg   196
#define MAXT 3200    // 25 * 128 >= T=3136
#define QT   128     // queries per flash block
#define KTILE 128    // keys per cp.async stage
#define KP   72      // attention smem pitch (bf16); 144B rows
#define AST  18432   // bytes per K/V array per stage (128*144)
#define STAGE (4 * AST)
#define FLASH_SMEM (2 * STAGE)

// bf16 scratch: 14 token-arrays [MAXT][Dm] + 8 weight arrays [Dm][Dm] (~50MB)
__device__ __nv_bfloat16 g_bf[14 * MAXT * Dm + 8 * Dm * Dm];
__device__ int g_sched[256];

__device__ __forceinline__ uint32_t smem_u32(const void* p) {
    uint32_t a;
    asm("{ .reg .u64 t; cvta.to.shared.u64 t, %1; cvt.u32.u64 %0, t; }" : "=r"(a) : "l"(p));
    return a;
}
__device__ __forceinline__ void ldsm_x4(uint32_t* r, uint32_t addr) {
    asm volatile("ldmatrix.sync.aligned.m8n8.x4.shared.b16 {%0,%1,%2,%3}, [%4];"
                 : "=r"(r[0]), "=r"(r[1]), "=r"(r[2]), "=r"(r[3]) : "r"(addr));
}
__device__ __forceinline__ void ldsm_x4_t(uint32_t* r, uint32_t addr) {
    asm volatile("ldmatrix.sync.aligned.m8n8.x4.trans.shared.b16 {%0,%1,%2,%3}, [%4];"
                 : "=r"(r[0]), "=r"(r[1]), "=r"(r[2]), "=r"(r[3]) : "r"(addr));
}
__device__ __forceinline__ void mma_bf16(float* c, const uint32_t* a, uint32_t b0, uint32_t b1) {
    asm volatile("mma.sync.aligned.m16n8k16.row.col.f32.bf16.bf16.f32 "
                 "{%0,%1,%2,%3}, {%4,%5,%6,%7}, {%8,%9}, {%0,%1,%2,%3};"
                 : "+f"(c[0]), "+f"(c[1]), "+f"(c[2]), "+f"(c[3])
                 : "r"(a[0]), "r"(a[1]), "r"(a[2]), "r"(a[3]), "r"(b0), "r"(b1));
}
__device__ __forceinline__ uint32_t pack2(__nv_bfloat16 x, __nv_bfloat16 y) {
    __nv_bfloat162 t(x, y);
    return *(uint32_t*)&t;
}
__device__ __forceinline__ void split2(float x, float y, uint32_t& hi, uint32_t& lo) {
    __nv_bfloat16 hx = __float2bfloat16(x), hy = __float2bfloat16(y);
    __nv_bfloat16 lx = __float2bfloat16(x - __bfloat162float(hx));
    __nv_bfloat16 ly = __float2bfloat16(y - __bfloat162float(hy));
    hi = pack2(hx, hy);
    lo = pack2(lx, ly);
}

// ---------------------------------------------------------------------------
// Input convert + (thread 0) schedule build, sorted longest-segment-first.
// ---------------------------------------------------------------------------
__global__ void conv_in(const float* __restrict__ xq, const float* __restrict__ xk,
                        const float* __restrict__ pos,
                        __nv_bfloat16* XQh, __nv_bfloat16* XQl,
                        __nv_bfloat16* XPh, __nv_bfloat16* XPl,
                        __nv_bfloat16* XKh, __nv_bfloat16* XKl, int n4,
                        const int* __restrict__ channels, int n_ch,
                        int* __restrict__ sched) {
    if (blockIdx.x == 0 && threadIdx.x == 0) {
        int e_q0[32], e_ql[32], e_bg[32], e_en[32];
        int cnt = 0, beg = 0;
        for (int i = 0; i < n_ch; i++) {
            int len = channels[i] * Sg, end = beg + len;
            for (int j = 0; j < len; j += QT) {
                e_q0[cnt] = beg + j;
                e_ql[cnt] = (len - j < QT) ? (len - j) : QT;
                e_bg[cnt] = beg;
                e_en[cnt] = end;
                cnt++;
            }
            beg = end;
        }
        // insertion sort by segment length descending
        for (int i = 1; i < cnt; i++) {
            int a = e_q0[i], b = e_ql[i], c = e_bg[i], d = e_en[i];
            int key = d - c, j = i - 1;
            while (j >= 0 && (e_en[j] - e_bg[j]) < key) {
                e_q0[j + 1] = e_q0[j]; e_ql[j + 1] = e_ql[j];
                e_bg[j + 1] = e_bg[j]; e_en[j + 1] = e_en[j];
                j--;
            }
            e_q0[j + 1] = a; e_ql[j + 1] = b; e_bg[j + 1] = c; e_en[j + 1] = d;
        }
        sched[0] = cnt;
        for (int i = 0; i < cnt; i++) {
            sched[1 + i * 4 + 0] = e_q0[i];
            sched[1 + i * 4 + 1] = e_ql[i];
            sched[1 + i * 4 + 2] = e_bg[i];
            sched[1 + i * 4 + 3] = e_en[i];
        }
    }
    int i = blockIdx.x * blockDim.x + threadIdx.x;
    if (i >= n4) return;
    float4 q = ((const float4*)xq)[i];
    float4 k = ((const float4*)xk)[i];
    float4 p = ((const float4*)pos)[i];
    uint32_t h0, l0, h1, l1;
    split2(q.x + p.x, q.y + p.y, h0, l0);
    split2(q.z + p.z, q.w + p.w, h1, l1);
    *(uint2*)&XQh[i * 4] = make_uint2(h0, h1);
    *(uint2*)&XQl[i * 4] = make_uint2(l0, l1);
    split2(k.x + p.x, k.y + p.y, h0, l0);
    split2(k.z + p.z, k.w + p.w, h1, l1);
    *(uint2*)&XPh[i * 4] = make_uint2(h0, h1);
    *(uint2*)&XPl[i * 4] = make_uint2(l0, l1);
    split2(k.x, k.y, h0, l0);
    split2(k.z, k.w, h1, l1);
    *(uint2*)&XKh[i * 4] = make_uint2(h0, h1);
    *(uint2*)&XKl[i * 4] = make_uint2(l0, l1);
}

// ---------------------------------------------------------------------------
// Weight transpose-convert: W[k][n] fp32 -> Wt[n][k] bf16 hi/lo.
// ---------------------------------------------------------------------------
struct WcArgs {
    const float* W[4];
    __nv_bfloat16* Wh[4];
    __nv_bfloat16* Wl[4];
};
__global__ void conv_w(WcArgs wa) {
    __shared__ float t[32][33];
    const float* W = wa.W[blockIdx.z];
    __nv_bfloat16* Wh = wa.Wh[blockIdx.z];
    __nv_bfloat16* Wl = wa.Wl[blockIdx.z];
    int n0 = blockIdx.x * 32, k0 = blockIdx.y * 32;
    int tx = threadIdx.x, ty = threadIdx.y;
#pragma unroll
    for (int i = 0; i < 4; i++)
        t[ty + i * 8][tx] = W[(size_t)(k0 + ty + i * 8) * Dm + n0 + tx];
    __syncthreads();
#pragma unroll
    for (int i = 0; i < 4; i++) {
        int n = n0 + ty + i * 8;
        float v = t[tx][ty + i * 8];
        __nv_bfloat16 h = __float2bfloat16(v);
        __nv_bfloat16 l = __float2bfloat16(v - __bfloat162float(h));
        Wh[(size_t)n * Dm + k0 + tx] = h;
        Wl[(size_t)n * Dm + k0 + tx] = l;
    }
}

// ---------------------------------------------------------------------------
// Pure-bf16 split-precision GEMM, cp.async double-buffered (validated R7).
// ---------------------------------------------------------------------------
struct GemmArgs {
    const __nv_bfloat16 *Ah[3], *Al[3], *Wh[3], *Wl[3];
    const float* bias[3];
    __nv_bfloat16 *Ch[3], *Cl[3];
    float* Cf[3];
};
#define STG 49152
#define GEMM_SMEM (2 * STG)

__global__ __launch_bounds__(256, 2)
void gemm_bf16(GemmArgs ga, int M) {
    extern __shared__ char sg[];
    const int z = blockIdx.z;
    const __nv_bfloat16* Ah = ga.Ah[z];
    const __nv_bfloat16* Al = ga.Al[z];
    const __nv_bfloat16* Wh = ga.Wh[z];
    const __nv_bfloat16* Wl = ga.Wl[z];
    const int tid = threadIdx.x, wid = tid >> 5, lane = tid & 31;
    const int m0 = blockIdx.x * 128, n0 = blockIdx.y * 64;
    const int wm = (wid & 3) * 32, wn = (wid >> 2) * 32;
    const uint32_t sb = smem_u32(sg);

    float acc[2][4][4];
#pragma unroll
    for (int i = 0; i < 2; i++)
#pragma unroll
        for (int j = 0; j < 4; j++)
#pragma unroll
            for (int q = 0; q < 4; q++) acc[i][j][q] = 0.f;

    auto ISSUE = [&](int c, int buf) {
        const uint32_t base = sb + buf * STG;
        const int ko = c * 64;
#pragma unroll
        for (int i = 0; i < 8; i++) {
            int idx = tid + i * 256;
            int arr = idx >> 10, rem = idx & 1023;
            int row = rem >> 3, g = rem & 7;
            uint32_t dst = base + arr * 16384 + row * 128 + ((g ^ (row & 7)) * 16);
            const __nv_bfloat16* src = (arr ? Al : Ah) + (size_t)(m0 + row) * Dm + ko + g * 8;
            int sz = (m0 + row) < M ? 16 : 0;
            asm volatile("cp.async.cg.shared.global [%0], [%1], 16, %2;"
                         :: "r"(dst), "l"(src), "r"(sz));
        }
#pragma unroll
        for (int i = 0; i < 4; i++) {
            int idx = tid + i * 256;
            int arr = idx >> 9, rem = idx & 511;
            int row = rem >> 3, g = rem & 7;
            uint32_t dst = base + 32768 + arr * 8192 + row * 128 + ((g ^ (row & 7)) * 16);
            const __nv_bfloat16* src = (arr ? Wl : Wh) + (size_t)(n0 + row) * Dm + ko + g * 8;
            asm volatile("cp.async.cg.shared.global [%0], [%1], 16;"
                         :: "r"(dst), "l"(src));
        }
        asm volatile("cp.async.commit_group;");
    };

    ISSUE(0, 0);
    const int NC = Dm / 64;
    for (int c = 0; c < NC; c++) {
        if (c + 1 < NC) {
            ISSUE(c + 1, (c + 1) & 1);
            asm volatile("cp.async.wait_group 1;");
        } else {
            asm volatile("cp.async.wait_group 0;");
        }
        __syncthreads();

        const uint32_t base = sb + (c & 1) * STG;
        const uint32_t sAh = base, sAl = base + 16384;
        const uint32_t sBh = base + 32768, sBl = base + 40960;

#pragma unroll
        for (int ks = 0; ks < 4; ks++) {
            uint32_t ah[2][4], al[2][4], bh[2][4], bl[2][4];
#pragma unroll
            for (int im = 0; im < 2; im++) {
                int row = wm + im * 16 + (lane & 15);
                int g = ks * 2 + (lane >> 4);
                uint32_t off = row * 128 + ((g ^ (row & 7)) * 16);
                ldsm_x4(ah[im], sAh + off);
                ldsm_x4(al[im], sAl + off);
            }
#pragma unroll
            for (int ib = 0; ib < 2; ib++) {
                int rn = wn + ib * 16 + (lane >> 4) * 8 + (lane & 7);
                int g = ks * 2 + ((lane >> 3) & 1);
                uint32_t off = rn * 128 + ((g ^ (rn & 7)) * 16);
                ldsm_x4(bh[ib], sBh + off);
                ldsm_x4(bl[ib], sBl + off);
            }
#pragma unroll
            for (int im = 0; im < 2; im++)
#pragma unroll
                for (int ib = 0; ib < 2; ib++) {
                    mma_bf16(acc[im][ib * 2 + 0], ah[im], bh[ib][0], bh[ib][1]);
                    mma_bf16(acc[im][ib * 2 + 1], ah[im], bh[ib][2], bh[ib][3]);
                    mma_bf16(acc[im][ib * 2 + 0], ah[im], bl[ib][0], bl[ib][1]);
                    mma_bf16(acc[im][ib * 2 + 1], ah[im], bl[ib][2], bl[ib][3]);
                    mma_bf16(acc[im][ib * 2 + 0], al[im], bh[ib][0], bh[ib][1]);
                    mma_bf16(acc[im][ib * 2 + 1], al[im], bh[ib][2], bh[ib][3]);
                }
        }
        __syncthreads();
    }

    const float* bias = ga.bias[z];
    __nv_bfloat16* Ch = ga.Ch[z];
    __nv_bfloat16* Cl = ga.Cl[z];
    float* Cf = ga.Cf[z];
#pragma unroll
    for (int im = 0; im < 2; im++) {
#pragma unroll
        for (int ib = 0; ib < 4; ib++) {
            int col = n0 + wn + ib * 8 + (lane & 3) * 2;
            float2 bb = *(const float2*)(bias + col);
#pragma unroll
            for (int hf = 0; hf < 2; hf++) {
                int r = m0 + wm + im * 16 + (lane >> 2) + hf * 8;
                if (r >= M) continue;
                float ox = acc[im][ib][hf * 2 + 0] + bb.x;
                float oy = acc[im][ib][hf * 2 + 1] + bb.y;
                if (Cf)
                    *(float2*)(Cf + (size_t)r * Dm + col) = make_float2(ox, oy);
                if (Ch) {
                    uint32_t h, l;
                    split2(ox, oy, h, l);
                    *(uint32_t*)(Ch + (size_t)r * Dm + col) = h;
                    *(uint32_t*)(Cl + (size_t)r * Dm + col) = l;
                }
            }
        }
    }
}

// ---------------------------------------------------------------------------
// Flash attention, cp.async double-buffered 128-key stages,
// two 64-key compute sub-iterations per stage.
// ---------------------------------------------------------------------------
__global__ __launch_bounds__(256)
void flash_attn(const __nv_bfloat16* __restrict__ Qhi, const __nv_bfloat16* __restrict__ Qlo,
                const __nv_bfloat16* __restrict__ Khi, const __nv_bfloat16* __restrict__ Klo,
                const __nv_bfloat16* __restrict__ Vhi, const __nv_bfloat16* __restrict__ Vlo,
                __nv_bfloat16* __restrict__ Oh, __nv_bfloat16* __restrict__ Ol,
                const int* __restrict__ sched) {
    extern __shared__ char smc[];
    __nv_bfloat16* smem = (__nv_bfloat16*)smc;
    const int cnt = sched[0];
    if (blockIdx.x >= cnt) return;
    const int* e = sched + 1 + blockIdx.x * 4;
    const int q0 = e[0], qlen = e[1], beg = e[2], end = e[3];
    const int h = blockIdx.y;
    const int tid = threadIdx.x, wid = tid >> 5, lane = tid & 31;
    const int wm = wid * 16;
    const uint32_t sb = smem_u32(smem);

    // ---- Stage Q [128][64] hi/lo into stage-0 smem, grab frags ----
    {
        __nv_bfloat16* sQh = smem;
        __nv_bfloat16* sQl = smem + QT * KP;
#pragma unroll
        for (int i = 0; i < 4; i++) {
            int idx = tid + i * 256;
            int row = idx >> 3, g = idx & 7;
            uint4 h4 = make_uint4(0, 0, 0, 0), l4 = make_uint4(0, 0, 0, 0);
            if (row < qlen) {
                h4 = *(const uint4*)(Qhi + (size_t)(q0 + row) * Dm + h * HDd + g * 8);
                l4 = *(const uint4*)(Qlo + (size_t)(q0 + row) * Dm + h * HDd + g * 8);
            }
            *(uint4*)&sQh[row * KP + g * 8] = h4;
            *(uint4*)&sQl[row * KP + g * 8] = l4;
        }
        __syncthreads();
    }
    uint32_t qh[4][4], ql[4][4];
    {
        const uint32_t aQh = sb, aQl = sb + QT * KP * 2;
#pragma unroll
        for (int ks = 0; ks < 4; ks++) {
            uint32_t ar = 2 * ((wm + (lane & 15)) * KP + ks * 16 + (lane >> 4) * 8);
            ldsm_x4(qh[ks], aQh + ar);
            ldsm_x4(ql[ks], aQl + ar);
        }
    }
    __syncthreads();

    // ---- cp.async K/V stage issue ----
    auto ISSUE = [&](int kt, int buf) {
        const int j0 = beg + kt * KTILE;
        const uint32_t base = sb + buf * STAGE;
#pragma unroll
        for (int i = 0; i < 16; i++) {
            const int arr = i >> 2;                  // 0:Kh 1:Kl 2:Vh 3:Vl
            int rem = tid + (i & 3) * 256;           // 0..1023
            int row = rem >> 3, g = rem & 7;
            int key = j0 + row;
            const __nv_bfloat16* p = (arr == 0) ? Khi : (arr == 1) ? Klo
                                   : (arr == 2) ? Vhi : Vlo;
            uint32_t dst = base + arr * AST + row * 144 + g * 16;
            const __nv_bfloat16* src = p + (size_t)key * Dm + h * HDd + g * 8;
            int sz = (key < end) ? 16 : 0;
            asm volatile("cp.async.cg.shared.global [%0], [%1], 16, %2;"
                         :: "r"(dst), "l"(src), "r"(sz));
        }
        asm volatile("cp.async.commit_group;");
    };

    float oacc[8][4];
#pragma unroll
    for (int t = 0; t < 8; t++)
#pragma unroll
        for (int j = 0; j < 4; j++) oacc[t][j] = 0.f;
    float mrow[2] = {-1e30f, -1e30f}, lrow[2] = {0.f, 0.f};

    const int nkt = (end - beg + KTILE - 1) / KTILE;
    ISSUE(0, 0);
    for (int kt = 0; kt < nkt; kt++) {
        if (kt + 1 < nkt) {
            ISSUE(kt + 1, (kt + 1) & 1);
            asm volatile("cp.async.wait_group 1;");
        } else {
            asm volatile("cp.async.wait_group 0;");
        }
        __syncthreads();

        const uint32_t stg = sb + (kt & 1) * STAGE;
#pragma unroll
        for (int sub = 0; sub < 2; sub++) {
            const int j0 = beg + kt * KTILE + sub * 64;
            if (j0 >= end) break;
            const uint32_t soff = sub * 64 * 144;
            const uint32_t aKh = stg + soff, aKl = stg + AST + soff;
            const uint32_t aVh = stg + 2 * AST + soff, aVl = stg + 3 * AST + soff;

            // ---- S = Q K^T ----
            float c[8][4];
#pragma unroll
            for (int t = 0; t < 8; t++)
#pragma unroll
                for (int j = 0; j < 4; j++) c[t][j] = 0.f;
#pragma unroll
            for (int ks = 0; ks < 4; ks++) {
#pragma unroll
                for (int nb = 0; nb < 4; nb++) {
                    uint32_t br = 2 * ((nb * 16 + (lane >> 4) * 8 + (lane & 7)) * KP +
                                       ks * 16 + ((lane >> 3) & 1) * 8);
                    uint32_t bh[4], bl[4];
                    ldsm_x4(bh, aKh + br);
                    ldsm_x4(bl, aKl + br);
                    mma_bf16(c[2 * nb], qh[ks], bh[0], bh[1]);
                    mma_bf16(c[2 * nb], qh[ks], bl[0], bl[1]);
                    mma_bf16(c[2 * nb], ql[ks], bh[0], bh[1]);
                    mma_bf16(c[2 * nb + 1], qh[ks], bh[2], bh[3]);
                    mma_bf16(c[2 * nb + 1], qh[ks], bl[2], bl[3]);
                    mma_bf16(c[2 * nb + 1], ql[ks], bh[2], bh[3]);
                }
            }

            // ---- mask + scale ----
#pragma unroll
            for (int t = 0; t < 8; t++) {
                int k0 = j0 + t * 8 + (lane & 3) * 2;
                bool v0 = k0 < end, v1 = k0 + 1 < end;
                c[t][0] = v0 ? c[t][0] * 0.125f : -1e30f;
                c[t][1] = v1 ? c[t][1] * 0.125f : -1e30f;
                c[t][2] = v0 ? c[t][2] * 0.125f : -1e30f;
                c[t][3] = v1 ? c[t][3] * 0.125f : -1e30f;
            }

            // ---- online softmax ----
#pragma unroll
            for (int rh = 0; rh < 2; rh++) {
                const int i0 = rh * 2;
                float mx = -1e30f;
#pragma unroll
                for (int t = 0; t < 8; t++)
                    mx = fmaxf(mx, fmaxf(c[t][i0], c[t][i0 + 1]));
                mx = fmaxf(mx, __shfl_xor_sync(0xffffffffu, mx, 1));
                mx = fmaxf(mx, __shfl_xor_sync(0xffffffffu, mx, 2));
                float mnew = fmaxf(mrow[rh], mx);
                float alpha = __expf(mrow[rh] - mnew);
                float ps = 0.f;
#pragma unroll
                for (int t = 0; t < 8; t++) {
                    float p0 = __expf(c[t][i0] - mnew);
                    float p1 = __expf(c[t][i0 + 1] - mnew);
                    c[t][i0] = p0;
                    c[t][i0 + 1] = p1;
                    ps += p0 + p1;
                }
                ps += __shfl_xor_sync(0xffffffffu, ps, 1);
                ps += __shfl_xor_sync(0xffffffffu, ps, 2);
                lrow[rh] = lrow[rh] * alpha + ps;
                mrow[rh] = mnew;
#pragma unroll
                for (int t = 0; t < 8; t++) {
                    oacc[t][i0] *= alpha;
                    oacc[t][i0 + 1] *= alpha;
                }
            }

            // ---- P -> A-frags (hi/lo) ----
            uint32_t ph[4][4], pl[4][4];
#pragma unroll
            for (int s = 0; s < 4; s++) {
                int t0 = 2 * s, t1 = 2 * s + 1;
                split2(c[t0][0], c[t0][1], ph[s][0], pl[s][0]);
                split2(c[t0][2], c[t0][3], ph[s][1], pl[s][1]);
                split2(c[t1][0], c[t1][1], ph[s][2], pl[s][2]);
                split2(c[t1][2], c[t1][3], ph[s][3], pl[s][3]);
            }

            // ---- O += P V ----
#pragma unroll
            for (int s = 0; s < 4; s++) {
                int mat = lane >> 3, rin = lane & 7;
                int keyr = s * 16 + (mat & 1) * 8 + rin;
#pragma unroll
                for (int d = 0; d < 4; d++) {
                    uint32_t ad = 2 * (keyr * KP + d * 16 + (mat >> 1) * 8);
                    uint32_t vh[4], vl[4];
                    ldsm_x4_t(vh, aVh + ad);
                    ldsm_x4_t(vl, aVl + ad);
                    mma_bf16(oacc[2 * d], ph[s], vh[0], vh[1]);
                    mma_bf16(oacc[2 * d], ph[s], vl[0], vl[1]);
                    mma_bf16(oacc[2 * d], pl[s], vh[0], vh[1]);
                    mma_bf16(oacc[2 * d + 1], ph[s], vh[2], vh[3]);
                    mma_bf16(oacc[2 * d + 1], ph[s], vl[2], vl[3]);
                    mma_bf16(oacc[2 * d + 1], pl[s], vh[2], vh[3]);
                }
            }
        }
        __syncthreads();
    }

    // ---- normalize + write bf16 hi/lo ----
#pragma unroll
    for (int rh = 0; rh < 2; rh++) {
        float inv = 1.f / lrow[rh];
        int row = wm + (lane >> 2) + rh * 8;
        if (row >= qlen) continue;
#pragma unroll
        for (int t = 0; t < 8; t++) {
            int col = h * HDd + t * 8 + (lane & 3) * 2;
            uint32_t hh, ll;
            split2(oacc[t][rh * 2] * inv, oacc[t][rh * 2 + 1] * inv, hh, ll);
            *(uint32_t*)(Oh + (size_t)(q0 + row) * Dm + col) = hh;
            *(uint32_t*)(Ol + (size_t)(q0 + row) * Dm + col) = ll;
        }
    }
}

// ---------------------------------------------------------------------------
extern "C" void kernel_launch(void* const* d_in, const int* in_sizes, int n_in,
                              void* d_out, int out_size) {
    const float* xq  = (const float*)d_in[0];
    const float* xk  = (const float*)d_in[1];
    const float* pos = (const float*)d_in[2];
    const int*   ch  = (const int*)d_in[3];
    const float* Wq = (const float*)d_in[4];  const float* bq = (const float*)d_in[5];
    const float* Wk = (const float*)d_in[6];  const float* bk = (const float*)d_in[7];
    const float* Wv = (const float*)d_in[8];  const float* bv = (const float*)d_in[9];
    const float* Wo = (const float*)d_in[10]; const float* bo = (const float*)d_in[11];
    float* out = (float*)d_out;

    const int T = in_sizes[0] / Dm;       // 3136
    const int n_ch = in_sizes[3];         // 4

    void* p = nullptr;
    cudaGetSymbolAddress(&p, g_bf);
    __nv_bfloat16* b = (__nv_bfloat16*)p;
    const size_t SZ = (size_t)MAXT * Dm;
    const size_t WZ = (size_t)Dm * Dm;
    __nv_bfloat16 *XQh = b + 0*SZ,  *XQl = b + 1*SZ;
    __nv_bfloat16 *XPh = b + 2*SZ,  *XPl = b + 3*SZ;
    __nv_bfloat16 *XKh = b + 4*SZ,  *XKl = b + 5*SZ;
    __nv_bfloat16 *Qh  = b + 6*SZ,  *Ql  = b + 7*SZ;
    __nv_bfloat16 *Kh  = b + 8*SZ,  *Kl  = b + 9*SZ;
    __nv_bfloat16 *Vh  = b + 10*SZ, *Vl  = b + 11*SZ;
    __nv_bfloat16 *Oh  = b + 12*SZ, *Ol  = b + 13*SZ;
    __nv_bfloat16* w = b + 14*SZ;
    __nv_bfloat16 *Wqh = w + 0*WZ, *Wql = w + 1*WZ;
    __nv_bfloat16 *Wkh = w + 2*WZ, *Wkl = w + 3*WZ;
    __nv_bfloat16 *Wvh = w + 4*WZ, *Wvl = w + 5*WZ;
    __nv_bfloat16 *Woh = w + 6*WZ, *Wol = w + 7*WZ;

    void* ps = nullptr;
    cudaGetSymbolAddress(&ps, g_sched);
    int* sched = (int*)ps;

    cudaFuncSetAttribute(gemm_bf16, cudaFuncAttributeMaxDynamicSharedMemorySize, GEMM_SMEM);
    cudaFuncSetAttribute(flash_attn, cudaFuncAttributeMaxDynamicSharedMemorySize, FLASH_SMEM);

    int n4 = T * Dm / 4;
    conv_in<<<(n4 + 255) / 256, 256>>>(xq, xk, pos, XQh, XQl, XPh, XPl, XKh, XKl, n4,
                                       ch, n_ch, sched);

    WcArgs wa;
    wa.W[0] = Wq; wa.Wh[0] = Wqh; wa.Wl[0] = Wql;
    wa.W[1] = Wk; wa.Wh[1] = Wkh; wa.Wl[1] = Wkl;
    wa.W[2] = Wv; wa.Wh[2] = Wvh; wa.Wl[2] = Wvl;
    wa.W[3] = Wo; wa.Wh[3] = Woh; wa.Wl[3] = Wol;
    conv_w<<<dim3(16, 16, 4), dim3(32, 8)>>>(wa);

    GemmArgs g1;
    g1.Ah[0] = XQh; g1.Al[0] = XQl; g1.Wh[0] = Wqh; g1.Wl[0] = Wql;
    g1.bias[0] = bq; g1.Ch[0] = Qh; g1.Cl[0] = Ql; g1.Cf[0] = nullptr;
    g1.Ah[1] = XPh; g1.Al[1] = XPl; g1.Wh[1] = Wkh; g1.Wl[1] = Wkl;
    g1.bias[1] = bk; g1.Ch[1] = Kh; g1.Cl[1] = Kl; g1.Cf[1] = nullptr;
    g1.Ah[2] = XKh; g1.Al[2] = XKl; g1.Wh[2] = Wvh; g1.Wl[2] = Wvl;
    g1.bias[2] = bv; g1.Ch[2] = Vh; g1.Cl[2] = Vl; g1.Cf[2] = nullptr;
    gemm_bf16<<<dim3(MAXT / 128, Dm / 64, 3), 256, GEMM_SMEM>>>(g1, T);

    dim3 ga(T / QT + n_ch, Hn);
    flash_attn<<<ga, 256, FLASH_SMEM>>>(Qh, Ql, Kh, Kl, Vh, Vl, Oh, Ol, sched);

    GemmArgs g2;
    g2.Ah[0] = Oh; g2.Al[0] = Ol; g2.Wh[0] = Woh; g2.Wl[0] = Wol;
    g2.bias[0] = bo; g2.Ch[0] = nullptr; g2.Cl[0] = nullptr; g2.Cf[0] = out;
    for (int i = 1; i < 3; i++) {
        g2.Ah[i] = Oh; g2.Al[i] = Ol; g2.Wh[i] = Woh; g2.Wl[i] = Wol;
        g2.bias[i] = bo; g2.Ch[i] = nullptr; g2.Cl[i] = nullptr; g2.Cf[i] = nullptr;
    }
    gemm_bf16<<<dim3(MAXT / 128, Dm / 64, 1), 256, GEMM_SMEM>>>(g2, T);
}